// round 10
// baseline (speedup 1.0000x reference)
#include <cuda_runtime.h>
#include <math.h>

#define B_ 8
#define T_ 2048
#define C_ 1024
#define H_ 64
#define NROWS (B_ * T_)   // 16384

__device__ float g_q[NROWS * H_];
__device__ float g_k[NROWS * H_];
__device__ float g_v[NROWS * H_];
__device__ float g_res[NROWS * H_];
__device__ float g_rowsum[NROWS];
__device__ float g_attn_scratch[(size_t)B_ * T_ * T_];

// ---- tf32 helpers -----------------------------------------------------------
__device__ __forceinline__ unsigned tf32(float f) {
    unsigned r;
    asm("cvt.rna.tf32.f32 %0, %1;" : "=r"(r) : "f"(f));
    return r;
}
__device__ __forceinline__ uint4 tf32x4(float4 f) {
    uint4 u;
    u.x = tf32(f.x); u.y = tf32(f.y); u.z = tf32(f.z); u.w = tf32(f.w);
    return u;
}
// D += A(16x8,row) * B(8x8,col); tf32 in, fp32 accum
__device__ __forceinline__ void mma8(float* c, const unsigned* a, const unsigned* b) {
    asm("mma.sync.aligned.m16n8k8.row.col.f32.tf32.tf32.f32 "
        "{%0,%1,%2,%3},{%4,%5,%6,%7},{%8,%9},{%0,%1,%2,%3};"
        : "+f"(c[0]), "+f"(c[1]), "+f"(c[2]), "+f"(c[3])
        : "r"(a[0]), "r"(a[1]), "r"(a[2]), "r"(a[3]), "r"(b[0]), "r"(b[1]));
}

// ---------------------------------------------------------------------------
// Kernel 1: QKV projection. grid=(256, 3) = 768 CTAs (5.2/SM), block=128.
// Block tile 64m x 64h, K-chunk 64. Warp tile 32m x 32h (mi=2, nj=4).
// smem 35KB -> 6 CTAs/SM; occupancy now grid-limited at ~5 CTAs/SM.
// ---------------------------------------------------------------------------
#define PROJ_SMEM (64 * 68 * 4 + 64 * 72 * 4)   // 35840 B
__global__ __launch_bounds__(128) void proj_kernel(const float* __restrict__ x,
                                                   const float* __restrict__ Wq,
                                                   const float* __restrict__ Wk,
                                                   const float* __restrict__ Wv) {
    extern __shared__ unsigned smu[];
    unsigned* Xs = smu;            // [64][68]
    unsigned* Ws = smu + 64 * 68;  // [64][72]

    const float* W; float* out;
    if (blockIdx.y == 0)      { W = Wq; out = g_q; }
    else if (blockIdx.y == 1) { W = Wk; out = g_k; }
    else                      { W = Wv; out = g_v; }

    const int row0 = blockIdx.x * 64;
    const int tid  = threadIdx.x;
    const int warp = tid >> 5;
    const int lane = tid & 31;
    const int g    = lane >> 2;    // 0..7
    const int tig  = lane & 3;     // 0..3
    const int wm   = warp >> 1;    // 0..1 (m)
    const int wn   = warp & 1;     // 0..1 (n)

    float acc[2][4][4] = {};

    for (int k0 = 0; k0 < C_; k0 += 64) {
        #pragma unroll
        for (int it = 0; it < 8; it++) {
            int idx = tid + it * 128;         // 1024 float4 = 64 x 16
            int r = idx >> 4, c4 = idx & 15;
            *(uint4*)&Xs[r * 68 + c4 * 4] =
                tf32x4(*(const float4*)&x[(size_t)(row0 + r) * C_ + k0 + c4 * 4]);
        }
        #pragma unroll
        for (int it = 0; it < 8; it++) {
            int idx = tid + it * 128;         // 1024 float4 = 64 x 16
            int r = idx >> 4, c4 = idx & 15;
            *(uint4*)&Ws[r * 72 + c4 * 4] =
                tf32x4(*(const float4*)&W[(size_t)(k0 + r) * H_ + c4 * 4]);
        }
        __syncthreads();

        #pragma unroll
        for (int k8 = 0; k8 < 8; k8++) {
            const int kb = k8 * 8;
            unsigned a[2][4];
            #pragma unroll
            for (int mi = 0; mi < 2; mi++) {
                int m0 = wm * 32 + mi * 16;
                a[mi][0] = Xs[(m0 + g) * 68 + kb + tig];
                a[mi][1] = Xs[(m0 + g + 8) * 68 + kb + tig];
                a[mi][2] = Xs[(m0 + g) * 68 + kb + tig + 4];
                a[mi][3] = Xs[(m0 + g + 8) * 68 + kb + tig + 4];
            }
            #pragma unroll
            for (int nj = 0; nj < 4; nj++) {
                int n0 = wn * 32 + nj * 8;
                unsigned b[2];
                b[0] = Ws[(kb + tig) * 72 + n0 + g];
                b[1] = Ws[(kb + tig + 4) * 72 + n0 + g];
                #pragma unroll
                for (int mi = 0; mi < 2; mi++) mma8(acc[mi][nj], a[mi], b);
            }
        }
        __syncthreads();
    }

    #pragma unroll
    for (int mi = 0; mi < 2; mi++) {
        #pragma unroll
        for (int nj = 0; nj < 4; nj++) {
            int m0 = row0 + wm * 32 + mi * 16;
            int n0 = wn * 32 + nj * 8 + tig * 2;
            float* c = acc[mi][nj];
            *(float2*)&out[(size_t)(m0 + g) * H_ + n0]     = make_float2(c[0], c[1]);
            *(float2*)&out[(size_t)(m0 + g + 8) * H_ + n0] = make_float2(c[2], c[3]);
        }
    }
}

// ---------------------------------------------------------------------------
// Kernel 2: E = exp(Q@K^T / 32) lower tiles (zeros upper), rowsum atomics.
// grid=(16 s,32 t,8 b), block=128 (4 warps along s). Tile 64t x 128s.
// (unchanged, known-good)
// ---------------------------------------------------------------------------
#define SCORES_SMEM (64 * 68 * 4 + 128 * 68 * 4)   // 52224 B
__global__ __launch_bounds__(128, 4) void scores_kernel(float* __restrict__ attn) {
    const int s_t = blockIdx.x, t_t = blockIdx.y;
    const int b = blockIdx.z;
    const int t0 = t_t * 64, s0 = s_t * 128;
    const int tid = threadIdx.x;

    if (s0 > t0 + 63) {  // strictly-upper tile: zero fill
        #pragma unroll
        for (int it = 0; it < 16; it++) {
            int idx = tid + it * 128;       // 2048 quads = 64 x 32
            int r = idx >> 5, c4 = idx & 31;
            *(float4*)&attn[((size_t)b * T_ + t0 + r) * T_ + s0 + c4 * 4] =
                make_float4(0.f, 0.f, 0.f, 0.f);
        }
        return;
    }

    extern __shared__ unsigned smu[];
    unsigned* Qs = smu;            // [64][68]
    unsigned* Ks = smu + 64 * 68;  // [128][68]

    const float* q = g_q + (size_t)b * T_ * H_;
    const float* k = g_k + (size_t)b * T_ * H_;

    #pragma unroll
    for (int it = 0; it < 8; it++) {
        int idx = tid + it * 128;          // 1024 float4 = 64 x 16
        int r = idx >> 4, c4 = idx & 15;
        *(uint4*)&Qs[r * 68 + c4 * 4] =
            tf32x4(*(const float4*)&q[(size_t)(t0 + r) * H_ + c4 * 4]);
    }
    #pragma unroll
    for (int it = 0; it < 16; it++) {
        int idx = tid + it * 128;          // 2048 float4 = 128 x 16
        int r = idx >> 4, c4 = idx & 15;
        *(uint4*)&Ks[r * 68 + c4 * 4] =
            tf32x4(*(const float4*)&k[(size_t)(s0 + r) * H_ + c4 * 4]);
    }
    __syncthreads();

    const int warp = tid >> 5;
    const int lane = tid & 31;
    const int g    = lane >> 2;
    const int tig  = lane & 3;

    float acc[4][4][4] = {};
    #pragma unroll
    for (int k8 = 0; k8 < 8; k8++) {
        const int kb = k8 * 8;
        unsigned a[4][4];
        #pragma unroll
        for (int mi = 0; mi < 4; mi++) {
            int m0 = mi * 16;
            a[mi][0] = Qs[(m0 + g) * 68 + kb + tig];
            a[mi][1] = Qs[(m0 + g + 8) * 68 + kb + tig];
            a[mi][2] = Qs[(m0 + g) * 68 + kb + tig + 4];
            a[mi][3] = Qs[(m0 + g + 8) * 68 + kb + tig + 4];
        }
        #pragma unroll
        for (int nj = 0; nj < 4; nj++) {
            int n0 = warp * 32 + nj * 8;
            unsigned bb[2];
            bb[0] = Ks[(n0 + g) * 68 + kb + tig];
            bb[1] = Ks[(n0 + g) * 68 + kb + tig + 4];
            #pragma unroll
            for (int mi = 0; mi < 4; mi++) mma8(acc[mi][nj], a[mi], bb);
        }
    }

    const float sc = 0.03125f;  // 1/sqrt(1024)
    const bool need_mask = (s0 + 127 > t0);
    #pragma unroll
    for (int mi = 0; mi < 4; mi++) {
        const int trow0 = t0 + mi * 16 + g;
        const int trow1 = trow0 + 8;
        float rs0 = 0.f, rs1 = 0.f;
        #pragma unroll
        for (int nj = 0; nj < 4; nj++) {
            int col = s0 + warp * 32 + nj * 8 + tig * 2;
            float* c = acc[mi][nj];
            float e0 = (!need_mask || col     <= trow0) ? __expf(c[0] * sc) : 0.f;
            float e1 = (!need_mask || col + 1 <= trow0) ? __expf(c[1] * sc) : 0.f;
            float e2 = (!need_mask || col     <= trow1) ? __expf(c[2] * sc) : 0.f;
            float e3 = (!need_mask || col + 1 <= trow1) ? __expf(c[3] * sc) : 0.f;
            rs0 += e0 + e1; rs1 += e2 + e3;
            *(float2*)&attn[((size_t)b * T_ + trow0) * T_ + col] = make_float2(e0, e1);
            *(float2*)&attn[((size_t)b * T_ + trow1) * T_ + col] = make_float2(e2, e3);
        }
        rs0 += __shfl_xor_sync(0xffffffffu, rs0, 1);
        rs0 += __shfl_xor_sync(0xffffffffu, rs0, 2);
        rs1 += __shfl_xor_sync(0xffffffffu, rs1, 1);
        rs1 += __shfl_xor_sync(0xffffffffu, rs1, 2);
        if (tig == 0) {
            atomicAdd(&g_rowsum[(size_t)b * T_ + trow0], rs0);
            atomicAdd(&g_rowsum[(size_t)b * T_ + trow1], rs1);
        }
    }
}

// ---------------------------------------------------------------------------
// Kernel 3: res += (attn/rowsum) @ V, split-K over 512-wide s-spans.
// Fused normalization. grid=(4 spans, 32 t desc, 8 b), block=128 (4 warps 2x2).
// Tile 64t x 64h. (unchanged, known-good)
// ---------------------------------------------------------------------------
#define AV_SMEM (64 * 68 * 4 + 64 * 72 * 4 + 64 * 4)   // 35904 B
__global__ __launch_bounds__(128, 5) void av_kernel(float* __restrict__ attn,
                                                    float* __restrict__ res) {
    const int sc   = blockIdx.x;
    const int t_t  = 31 - blockIdx.y;   // big tiles first
    const int b    = blockIdx.z;
    const int t0   = t_t * 64;
    if (sc * 512 > t0 + 63) return;

    extern __shared__ unsigned smu[];
    unsigned* As = smu;            // [64 t][68 s] tf32
    unsigned* Vs = smu + 64 * 68;  // [64 s][72 h] tf32
    float* sinv  = (float*)(smu + 64 * 68 + 64 * 72);

    const int tid = threadIdx.x;
    if (tid < 64) sinv[tid] = 1.f / g_rowsum[(size_t)b * T_ + t0 + tid];
    __syncthreads();

    const float* v = g_v + (size_t)b * T_ * H_;
    const int warp = tid >> 5;
    const int lane = tid & 31;
    const int g    = lane >> 2;
    const int tig  = lane & 3;
    const int wm   = warp >> 1;   // 0..1
    const int wn   = warp & 1;    // 0..1

    float acc[2][4][4] = {};

    #pragma unroll
    for (int c2 = 0; c2 < 8; c2++) {
        const int s0 = sc * 512 + c2 * 64;
        if (s0 > t0 + 63) break;

        #pragma unroll
        for (int it = 0; it < 8; it++) {
            int idx = tid + it * 128;          // 1024 float4 = 64 x 16
            int r = idx >> 4, c4 = idx & 15;
            float* ap = &attn[((size_t)b * T_ + t0 + r) * T_ + s0 + c4 * 4];
            float4 f = *(const float4*)ap;
            float iv = sinv[r];
            f = make_float4(f.x * iv, f.y * iv, f.z * iv, f.w * iv);
            *(float4*)ap = f;                  // normalized fp32 back to gmem
            *(uint4*)&As[r * 68 + c4 * 4] = tf32x4(f);
        }
        #pragma unroll
        for (int it = 0; it < 8; it++) {
            int idx = tid + it * 128;
            int r = idx >> 4, c4 = idx & 15;
            *(uint4*)&Vs[r * 72 + c4 * 4] =
                tf32x4(*(const float4*)&v[(size_t)(s0 + r) * H_ + c4 * 4]);
        }
        __syncthreads();

        #pragma unroll
        for (int k8 = 0; k8 < 8; k8++) {
            const int kb = k8 * 8;
            unsigned a[2][4];
            #pragma unroll
            for (int mi = 0; mi < 2; mi++) {
                int m0 = wm * 32 + mi * 16;
                a[mi][0] = As[(m0 + g) * 68 + kb + tig];
                a[mi][1] = As[(m0 + g + 8) * 68 + kb + tig];
                a[mi][2] = As[(m0 + g) * 68 + kb + tig + 4];
                a[mi][3] = As[(m0 + g + 8) * 68 + kb + tig + 4];
            }
            #pragma unroll
            for (int nj = 0; nj < 4; nj++) {
                int n0 = wn * 32 + nj * 8;
                unsigned bb[2];
                bb[0] = Vs[(kb + tig) * 72 + n0 + g];
                bb[1] = Vs[(kb + tig + 4) * 72 + n0 + g];
                #pragma unroll
                for (int mi = 0; mi < 2; mi++) mma8(acc[mi][nj], a[mi], bb);
            }
        }
        __syncthreads();
    }

    #pragma unroll
    for (int mi = 0; mi < 2; mi++) {
        #pragma unroll
        for (int nj = 0; nj < 4; nj++) {
            int m0 = t0 + wm * 32 + mi * 16;
            int n0 = wn * 32 + nj * 8 + tig * 2;
            float* c = acc[mi][nj];
            size_t r0 = ((size_t)b * T_ + m0 + g) * H_ + n0;
            size_t r1 = ((size_t)b * T_ + m0 + g + 8) * H_ + n0;
            atomicAdd(&res[r0],     c[0]);
            atomicAdd(&res[r0 + 1], c[1]);
            atomicAdd(&res[r1],     c[2]);
            atomicAdd(&res[r1 + 1], c[3]);
        }
    }
}

// ---------------------------------------------------------------------------
extern "C" void kernel_launch(void* const* d_in, const int* in_sizes, int n_in,
                              void* d_out, int out_size) {
    (void)in_sizes; (void)n_in;
    const float* x  = (const float*)d_in[0];
    const float* Wq = (const float*)d_in[1];
    const float* Wk = (const float*)d_in[2];
    const float* Wv = (const float*)d_in[3];

    const size_t n_res  = (size_t)B_ * T_ * H_;
    const size_t n_attn = (size_t)B_ * T_ * T_;

    float* attn_scratch = nullptr;
    float* res_scratch = nullptr;
    float* rowsum = nullptr;
    cudaGetSymbolAddress((void**)&attn_scratch, g_attn_scratch);
    cudaGetSymbolAddress((void**)&res_scratch, g_res);
    cudaGetSymbolAddress((void**)&rowsum, g_rowsum);

    float* res;
    float* attn;
    if ((size_t)out_size == n_res + n_attn) {
        res  = (float*)d_out;
        attn = (float*)d_out + n_res;
    } else if ((size_t)out_size == n_attn) {
        attn = (float*)d_out;
        res  = res_scratch;
    } else {
        res  = (float*)d_out;
        attn = attn_scratch;
    }

    cudaFuncSetAttribute(proj_kernel,   cudaFuncAttributeMaxDynamicSharedMemorySize, PROJ_SMEM);
    cudaFuncSetAttribute(scores_kernel, cudaFuncAttributeMaxDynamicSharedMemorySize, SCORES_SMEM);
    cudaFuncSetAttribute(av_kernel,     cudaFuncAttributeMaxDynamicSharedMemorySize, AV_SMEM);

    cudaMemsetAsync(rowsum, 0, NROWS * sizeof(float));
    cudaMemsetAsync(res, 0, n_res * sizeof(float));
    proj_kernel<<<dim3(256, 3), 128, PROJ_SMEM>>>(x, Wq, Wk, Wv);
    scores_kernel<<<dim3(16, 32, 8), 128, SCORES_SMEM>>>(attn);
    av_kernel<<<dim3(4, 32, 8), 128, AV_SMEM>>>(attn, res);
}

// round 11
// speedup vs baseline: 1.2225x; 1.2225x over previous
#include <cuda_runtime.h>
#include <math.h>

#define B_ 8
#define T_ 2048
#define C_ 1024
#define H_ 64
#define NROWS (B_ * T_)   // 16384

__device__ float g_q[NROWS * H_];
__device__ float g_k[NROWS * H_];
__device__ float g_v[NROWS * H_];
__device__ float g_res[NROWS * H_];
__device__ float g_rowsum[NROWS];
__device__ float g_attn_scratch[(size_t)B_ * T_ * T_];

// ---- tf32 helpers -----------------------------------------------------------
__device__ __forceinline__ unsigned tf32(float f) {
    unsigned r;
    asm("cvt.rna.tf32.f32 %0, %1;" : "=r"(r) : "f"(f));
    return r;
}
__device__ __forceinline__ uint4 tf32x4(float4 f) {
    uint4 u;
    u.x = tf32(f.x); u.y = tf32(f.y); u.z = tf32(f.z); u.w = tf32(f.w);
    return u;
}
// D += A(16x8,row) * B(8x8,col); tf32 in, fp32 accum
__device__ __forceinline__ void mma8(float* c, const unsigned* a, const unsigned* b) {
    asm("mma.sync.aligned.m16n8k8.row.col.f32.tf32.tf32.f32 "
        "{%0,%1,%2,%3},{%4,%5,%6,%7},{%8,%9},{%0,%1,%2,%3};"
        : "+f"(c[0]), "+f"(c[1]), "+f"(c[2]), "+f"(c[3])
        : "r"(a[0]), "r"(a[1]), "r"(a[2]), "r"(a[3]), "r"(b[0]), "r"(b[1]));
}

// ---------------------------------------------------------------------------
// Kernel 1: QKV projection, split-K x2. grid=(128, 3, 2) = 768 CTAs, block=128.
// Block tile 128m x 64h, K-range 512 per CTA (8 chunks of 64).
// Warp tile 64m x 32h (mi=4, nj=4). Epilogue: atomicAdd into zeroed outputs.
// ---------------------------------------------------------------------------
#define PROJ_SMEM (128 * 68 * 4 + 64 * 72 * 4)   // 53248 B
__global__ __launch_bounds__(128) void proj_kernel(const float* __restrict__ x,
                                                   const float* __restrict__ Wq,
                                                   const float* __restrict__ Wk,
                                                   const float* __restrict__ Wv) {
    extern __shared__ unsigned smu[];
    unsigned* Xs = smu;             // [128][68]
    unsigned* Ws = smu + 128 * 68;  // [64][72]

    const float* W; float* out;
    if (blockIdx.y == 0)      { W = Wq; out = g_q; }
    else if (blockIdx.y == 1) { W = Wk; out = g_k; }
    else                      { W = Wv; out = g_v; }

    const int row0 = blockIdx.x * 128;
    const int kbeg = blockIdx.z * 512;
    const int kend = kbeg + 512;
    const int tid  = threadIdx.x;
    const int warp = tid >> 5;
    const int lane = tid & 31;
    const int g    = lane >> 2;    // 0..7
    const int tig  = lane & 3;     // 0..3
    const int wm   = warp >> 1;    // 0..1 (m)
    const int wn   = warp & 1;     // 0..1 (n)

    float acc[4][4][4] = {};

    for (int k0 = kbeg; k0 < kend; k0 += 64) {
        #pragma unroll
        for (int it = 0; it < 16; it++) {
            int idx = tid + it * 128;         // 2048 float4 = 128 x 16
            int r = idx >> 4, c4 = idx & 15;
            *(uint4*)&Xs[r * 68 + c4 * 4] =
                tf32x4(*(const float4*)&x[(size_t)(row0 + r) * C_ + k0 + c4 * 4]);
        }
        #pragma unroll
        for (int it = 0; it < 8; it++) {
            int idx = tid + it * 128;         // 1024 float4 = 64 x 16
            int r = idx >> 4, c4 = idx & 15;
            *(uint4*)&Ws[r * 72 + c4 * 4] =
                tf32x4(*(const float4*)&W[(size_t)(k0 + r) * H_ + c4 * 4]);
        }
        __syncthreads();

        #pragma unroll
        for (int k8 = 0; k8 < 8; k8++) {
            const int kb = k8 * 8;
            unsigned a[4][4];
            #pragma unroll
            for (int mi = 0; mi < 4; mi++) {
                int m0 = wm * 64 + mi * 16;
                a[mi][0] = Xs[(m0 + g) * 68 + kb + tig];
                a[mi][1] = Xs[(m0 + g + 8) * 68 + kb + tig];
                a[mi][2] = Xs[(m0 + g) * 68 + kb + tig + 4];
                a[mi][3] = Xs[(m0 + g + 8) * 68 + kb + tig + 4];
            }
            #pragma unroll
            for (int nj = 0; nj < 4; nj++) {
                int n0 = wn * 32 + nj * 8;
                unsigned b[2];
                b[0] = Ws[(kb + tig) * 72 + n0 + g];
                b[1] = Ws[(kb + tig + 4) * 72 + n0 + g];
                #pragma unroll
                for (int mi = 0; mi < 4; mi++) mma8(acc[mi][nj], a[mi], b);
            }
        }
        __syncthreads();
    }

    #pragma unroll
    for (int mi = 0; mi < 4; mi++) {
        #pragma unroll
        for (int nj = 0; nj < 4; nj++) {
            int m0 = row0 + wm * 64 + mi * 16;
            int n0 = wn * 32 + nj * 8 + tig * 2;
            float* c = acc[mi][nj];
            size_t r0 = (size_t)(m0 + g) * H_ + n0;
            size_t r1 = (size_t)(m0 + g + 8) * H_ + n0;
            atomicAdd(&out[r0],     c[0]);
            atomicAdd(&out[r0 + 1], c[1]);
            atomicAdd(&out[r1],     c[2]);
            atomicAdd(&out[r1 + 1], c[3]);
        }
    }
}

// ---------------------------------------------------------------------------
// Kernel 2: E = exp(Q@K^T / 32) lower tiles (zeros upper), rowsum atomics.
// grid=(16 s,32 t,8 b), block=128 (4 warps along s). Tile 64t x 128s.
// (unchanged, known-good)
// ---------------------------------------------------------------------------
#define SCORES_SMEM (64 * 68 * 4 + 128 * 68 * 4)   // 52224 B
__global__ __launch_bounds__(128, 4) void scores_kernel(float* __restrict__ attn) {
    const int s_t = blockIdx.x, t_t = blockIdx.y;
    const int b = blockIdx.z;
    const int t0 = t_t * 64, s0 = s_t * 128;
    const int tid = threadIdx.x;

    if (s0 > t0 + 63) {  // strictly-upper tile: zero fill
        #pragma unroll
        for (int it = 0; it < 16; it++) {
            int idx = tid + it * 128;       // 2048 quads = 64 x 32
            int r = idx >> 5, c4 = idx & 31;
            *(float4*)&attn[((size_t)b * T_ + t0 + r) * T_ + s0 + c4 * 4] =
                make_float4(0.f, 0.f, 0.f, 0.f);
        }
        return;
    }

    extern __shared__ unsigned smu[];
    unsigned* Qs = smu;            // [64][68]
    unsigned* Ks = smu + 64 * 68;  // [128][68]

    const float* q = g_q + (size_t)b * T_ * H_;
    const float* k = g_k + (size_t)b * T_ * H_;

    #pragma unroll
    for (int it = 0; it < 8; it++) {
        int idx = tid + it * 128;          // 1024 float4 = 64 x 16
        int r = idx >> 4, c4 = idx & 15;
        *(uint4*)&Qs[r * 68 + c4 * 4] =
            tf32x4(*(const float4*)&q[(size_t)(t0 + r) * H_ + c4 * 4]);
    }
    #pragma unroll
    for (int it = 0; it < 16; it++) {
        int idx = tid + it * 128;          // 2048 float4 = 128 x 16
        int r = idx >> 4, c4 = idx & 15;
        *(uint4*)&Ks[r * 68 + c4 * 4] =
            tf32x4(*(const float4*)&k[(size_t)(s0 + r) * H_ + c4 * 4]);
    }
    __syncthreads();

    const int warp = tid >> 5;
    const int lane = tid & 31;
    const int g    = lane >> 2;
    const int tig  = lane & 3;

    float acc[4][4][4] = {};
    #pragma unroll
    for (int k8 = 0; k8 < 8; k8++) {
        const int kb = k8 * 8;
        unsigned a[4][4];
        #pragma unroll
        for (int mi = 0; mi < 4; mi++) {
            int m0 = mi * 16;
            a[mi][0] = Qs[(m0 + g) * 68 + kb + tig];
            a[mi][1] = Qs[(m0 + g + 8) * 68 + kb + tig];
            a[mi][2] = Qs[(m0 + g) * 68 + kb + tig + 4];
            a[mi][3] = Qs[(m0 + g + 8) * 68 + kb + tig + 4];
        }
        #pragma unroll
        for (int nj = 0; nj < 4; nj++) {
            int n0 = warp * 32 + nj * 8;
            unsigned bb[2];
            bb[0] = Ks[(n0 + g) * 68 + kb + tig];
            bb[1] = Ks[(n0 + g) * 68 + kb + tig + 4];
            #pragma unroll
            for (int mi = 0; mi < 4; mi++) mma8(acc[mi][nj], a[mi], bb);
        }
    }

    const float sc = 0.03125f;  // 1/sqrt(1024)
    const bool need_mask = (s0 + 127 > t0);
    #pragma unroll
    for (int mi = 0; mi < 4; mi++) {
        const int trow0 = t0 + mi * 16 + g;
        const int trow1 = trow0 + 8;
        float rs0 = 0.f, rs1 = 0.f;
        #pragma unroll
        for (int nj = 0; nj < 4; nj++) {
            int col = s0 + warp * 32 + nj * 8 + tig * 2;
            float* c = acc[mi][nj];
            float e0 = (!need_mask || col     <= trow0) ? __expf(c[0] * sc) : 0.f;
            float e1 = (!need_mask || col + 1 <= trow0) ? __expf(c[1] * sc) : 0.f;
            float e2 = (!need_mask || col     <= trow1) ? __expf(c[2] * sc) : 0.f;
            float e3 = (!need_mask || col + 1 <= trow1) ? __expf(c[3] * sc) : 0.f;
            rs0 += e0 + e1; rs1 += e2 + e3;
            *(float2*)&attn[((size_t)b * T_ + trow0) * T_ + col] = make_float2(e0, e1);
            *(float2*)&attn[((size_t)b * T_ + trow1) * T_ + col] = make_float2(e2, e3);
        }
        rs0 += __shfl_xor_sync(0xffffffffu, rs0, 1);
        rs0 += __shfl_xor_sync(0xffffffffu, rs0, 2);
        rs1 += __shfl_xor_sync(0xffffffffu, rs1, 1);
        rs1 += __shfl_xor_sync(0xffffffffu, rs1, 2);
        if (tig == 0) {
            atomicAdd(&g_rowsum[(size_t)b * T_ + trow0], rs0);
            atomicAdd(&g_rowsum[(size_t)b * T_ + trow1], rs1);
        }
    }
}

// ---------------------------------------------------------------------------
// Kernel 3: res += (attn/rowsum) @ V, split-K over 512-wide s-spans.
// Fused normalization. grid=(4 spans, 32 t desc, 8 b), block=128 (4 warps 2x2).
// Tile 64t x 64h. (unchanged, known-good)
// ---------------------------------------------------------------------------
#define AV_SMEM (64 * 68 * 4 + 64 * 72 * 4 + 64 * 4)   // 35904 B
__global__ __launch_bounds__(128, 5) void av_kernel(float* __restrict__ attn,
                                                    float* __restrict__ res) {
    const int sc   = blockIdx.x;
    const int t_t  = 31 - blockIdx.y;   // big tiles first
    const int b    = blockIdx.z;
    const int t0   = t_t * 64;
    if (sc * 512 > t0 + 63) return;

    extern __shared__ unsigned smu[];
    unsigned* As = smu;            // [64 t][68 s] tf32
    unsigned* Vs = smu + 64 * 68;  // [64 s][72 h] tf32
    float* sinv  = (float*)(smu + 64 * 68 + 64 * 72);

    const int tid = threadIdx.x;
    if (tid < 64) sinv[tid] = 1.f / g_rowsum[(size_t)b * T_ + t0 + tid];
    __syncthreads();

    const float* v = g_v + (size_t)b * T_ * H_;
    const int warp = tid >> 5;
    const int lane = tid & 31;
    const int g    = lane >> 2;
    const int tig  = lane & 3;
    const int wm   = warp >> 1;   // 0..1
    const int wn   = warp & 1;    // 0..1

    float acc[2][4][4] = {};

    #pragma unroll
    for (int c2 = 0; c2 < 8; c2++) {
        const int s0 = sc * 512 + c2 * 64;
        if (s0 > t0 + 63) break;

        #pragma unroll
        for (int it = 0; it < 8; it++) {
            int idx = tid + it * 128;          // 1024 float4 = 64 x 16
            int r = idx >> 4, c4 = idx & 15;
            float* ap = &attn[((size_t)b * T_ + t0 + r) * T_ + s0 + c4 * 4];
            float4 f = *(const float4*)ap;
            float iv = sinv[r];
            f = make_float4(f.x * iv, f.y * iv, f.z * iv, f.w * iv);
            *(float4*)ap = f;                  // normalized fp32 back to gmem
            *(uint4*)&As[r * 68 + c4 * 4] = tf32x4(f);
        }
        #pragma unroll
        for (int it = 0; it < 8; it++) {
            int idx = tid + it * 128;
            int r = idx >> 4, c4 = idx & 15;
            *(uint4*)&Vs[r * 72 + c4 * 4] =
                tf32x4(*(const float4*)&v[(size_t)(s0 + r) * H_ + c4 * 4]);
        }
        __syncthreads();

        #pragma unroll
        for (int k8 = 0; k8 < 8; k8++) {
            const int kb = k8 * 8;
            unsigned a[2][4];
            #pragma unroll
            for (int mi = 0; mi < 2; mi++) {
                int m0 = wm * 32 + mi * 16;
                a[mi][0] = As[(m0 + g) * 68 + kb + tig];
                a[mi][1] = As[(m0 + g + 8) * 68 + kb + tig];
                a[mi][2] = As[(m0 + g) * 68 + kb + tig + 4];
                a[mi][3] = As[(m0 + g + 8) * 68 + kb + tig + 4];
            }
            #pragma unroll
            for (int nj = 0; nj < 4; nj++) {
                int n0 = wn * 32 + nj * 8;
                unsigned bb[2];
                bb[0] = Vs[(kb + tig) * 72 + n0 + g];
                bb[1] = Vs[(kb + tig + 4) * 72 + n0 + g];
                #pragma unroll
                for (int mi = 0; mi < 2; mi++) mma8(acc[mi][nj], a[mi], bb);
            }
        }
        __syncthreads();
    }

    #pragma unroll
    for (int mi = 0; mi < 2; mi++) {
        #pragma unroll
        for (int nj = 0; nj < 4; nj++) {
            int m0 = t0 + wm * 32 + mi * 16;
            int n0 = wn * 32 + nj * 8 + tig * 2;
            float* c = acc[mi][nj];
            size_t r0 = ((size_t)b * T_ + m0 + g) * H_ + n0;
            size_t r1 = ((size_t)b * T_ + m0 + g + 8) * H_ + n0;
            atomicAdd(&res[r0],     c[0]);
            atomicAdd(&res[r0 + 1], c[1]);
            atomicAdd(&res[r1],     c[2]);
            atomicAdd(&res[r1 + 1], c[3]);
        }
    }
}

// ---------------------------------------------------------------------------
extern "C" void kernel_launch(void* const* d_in, const int* in_sizes, int n_in,
                              void* d_out, int out_size) {
    (void)in_sizes; (void)n_in;
    const float* x  = (const float*)d_in[0];
    const float* Wq = (const float*)d_in[1];
    const float* Wk = (const float*)d_in[2];
    const float* Wv = (const float*)d_in[3];

    const size_t n_res  = (size_t)B_ * T_ * H_;
    const size_t n_attn = (size_t)B_ * T_ * T_;

    float* attn_scratch = nullptr;
    float* res_scratch = nullptr;
    float* rowsum = nullptr;
    float* qp = nullptr; float* kp = nullptr; float* vp = nullptr;
    cudaGetSymbolAddress((void**)&attn_scratch, g_attn_scratch);
    cudaGetSymbolAddress((void**)&res_scratch, g_res);
    cudaGetSymbolAddress((void**)&rowsum, g_rowsum);
    cudaGetSymbolAddress((void**)&qp, g_q);
    cudaGetSymbolAddress((void**)&kp, g_k);
    cudaGetSymbolAddress((void**)&vp, g_v);

    float* res;
    float* attn;
    if ((size_t)out_size == n_res + n_attn) {
        res  = (float*)d_out;
        attn = (float*)d_out + n_res;
    } else if ((size_t)out_size == n_attn) {
        attn = (float*)d_out;
        res  = res_scratch;
    } else {
        res  = (float*)d_out;
        attn = attn_scratch;
    }

    cudaFuncSetAttribute(proj_kernel,   cudaFuncAttributeMaxDynamicSharedMemorySize, PROJ_SMEM);
    cudaFuncSetAttribute(scores_kernel, cudaFuncAttributeMaxDynamicSharedMemorySize, SCORES_SMEM);
    cudaFuncSetAttribute(av_kernel,     cudaFuncAttributeMaxDynamicSharedMemorySize, AV_SMEM);

    cudaMemsetAsync(rowsum, 0, NROWS * sizeof(float));
    cudaMemsetAsync(res, 0, n_res * sizeof(float));
    cudaMemsetAsync(qp, 0, n_res * sizeof(float));
    cudaMemsetAsync(kp, 0, n_res * sizeof(float));
    cudaMemsetAsync(vp, 0, n_res * sizeof(float));
    proj_kernel<<<dim3(128, 3, 2), 128, PROJ_SMEM>>>(x, Wq, Wk, Wv);
    scores_kernel<<<dim3(16, 32, 8), 128, SCORES_SMEM>>>(attn);
    av_kernel<<<dim3(4, 32, 8), 128, AV_SMEM>>>(attn, res);
}

// round 12
// speedup vs baseline: 1.5416x; 1.2610x over previous
#include <cuda_runtime.h>
#include <math.h>

#define B_ 8
#define T_ 2048
#define C_ 1024
#define H_ 64
#define NROWS (B_ * T_)   // 16384

__device__ float g_q[NROWS * H_];
__device__ float g_k[NROWS * H_];
__device__ float g_v[NROWS * H_];
__device__ float g_res[NROWS * H_];
__device__ float g_rowsum[NROWS];
__device__ float g_attn_scratch[(size_t)B_ * T_ * T_];

// ---- tf32 helpers -----------------------------------------------------------
__device__ __forceinline__ unsigned tf32(float f) {
    unsigned r;
    asm("cvt.rna.tf32.f32 %0, %1;" : "=r"(r) : "f"(f));
    return r;
}
__device__ __forceinline__ uint4 tf32x4(float4 f) {
    uint4 u;
    u.x = tf32(f.x); u.y = tf32(f.y); u.z = tf32(f.z); u.w = tf32(f.w);
    return u;
}
// D += A(16x8,row) * B(8x8,col); tf32 in, fp32 accum
__device__ __forceinline__ void mma8(float* c, const unsigned* a, const unsigned* b) {
    asm("mma.sync.aligned.m16n8k8.row.col.f32.tf32.tf32.f32 "
        "{%0,%1,%2,%3},{%4,%5,%6,%7},{%8,%9},{%0,%1,%2,%3};"
        : "+f"(c[0]), "+f"(c[1]), "+f"(c[2]), "+f"(c[3])
        : "r"(a[0]), "r"(a[1]), "r"(a[2]), "r"(a[3]), "r"(b[0]), "r"(b[1]));
}
// Load a full 16x8 tf32 A-fragment in one instruction.
// saddr (per-lane): base + ((m0 + (lane&15))*pitch + kb + (lane>>4)*4)*4 bytes
__device__ __forceinline__ void ldmA(unsigned* a, unsigned saddr) {
    asm volatile("ldmatrix.sync.aligned.m8n8.x4.shared.b16 {%0,%1,%2,%3}, [%4];"
        : "=r"(a[0]), "=r"(a[1]), "=r"(a[2]), "=r"(a[3]) : "r"(saddr));
}

// ---------------------------------------------------------------------------
// Kernel 1: QKV projection. grid=(128, 3), block=128 (4 warps: 2m x 2n).
// Block tile 128m x 64h, K-chunk 64. Warp tile 64m x 32h (mi=4, nj=4).
// A-fragments via ldmatrix.x4.
// ---------------------------------------------------------------------------
#define PROJ_SMEM (128 * 68 * 4 + 64 * 72 * 4)   // 53248 B
__global__ __launch_bounds__(128) void proj_kernel(const float* __restrict__ x,
                                                   const float* __restrict__ Wq,
                                                   const float* __restrict__ Wk,
                                                   const float* __restrict__ Wv) {
    extern __shared__ unsigned smu[];
    unsigned* Xs = smu;             // [128][68]
    unsigned* Ws = smu + 128 * 68;  // [64][72]

    const float* W; float* out;
    if (blockIdx.y == 0)      { W = Wq; out = g_q; }
    else if (blockIdx.y == 1) { W = Wk; out = g_k; }
    else                      { W = Wv; out = g_v; }

    const int row0 = blockIdx.x * 128;
    const int tid  = threadIdx.x;
    const int warp = tid >> 5;
    const int lane = tid & 31;
    const int g    = lane >> 2;    // 0..7
    const int tig  = lane & 3;     // 0..3
    const int wm   = warp >> 1;    // 0..1 (m)
    const int wn   = warp & 1;     // 0..1 (n)

    const unsigned xs_base = (unsigned)__cvta_generic_to_shared(Xs);
    const int lrow  = lane & 15;
    const int lkoff = (lane >> 4) * 4;

    float acc[4][4][4] = {};

    for (int k0 = 0; k0 < C_; k0 += 64) {
        #pragma unroll
        for (int it = 0; it < 16; it++) {
            int idx = tid + it * 128;         // 2048 float4 = 128 x 16
            int r = idx >> 4, c4 = idx & 15;
            *(uint4*)&Xs[r * 68 + c4 * 4] =
                tf32x4(*(const float4*)&x[(size_t)(row0 + r) * C_ + k0 + c4 * 4]);
        }
        #pragma unroll
        for (int it = 0; it < 8; it++) {
            int idx = tid + it * 128;         // 1024 float4 = 64 x 16
            int r = idx >> 4, c4 = idx & 15;
            *(uint4*)&Ws[r * 72 + c4 * 4] =
                tf32x4(*(const float4*)&W[(size_t)(k0 + r) * H_ + c4 * 4]);
        }
        __syncthreads();

        #pragma unroll
        for (int k8 = 0; k8 < 8; k8++) {
            const int kb = k8 * 8;
            unsigned a[4][4];
            #pragma unroll
            for (int mi = 0; mi < 4; mi++) {
                int m0 = wm * 64 + mi * 16;
                ldmA(a[mi], xs_base + (((m0 + lrow) * 68 + kb + lkoff) << 2));
            }
            #pragma unroll
            for (int nj = 0; nj < 4; nj++) {
                int n0 = wn * 32 + nj * 8;
                unsigned b[2];
                b[0] = Ws[(kb + tig) * 72 + n0 + g];
                b[1] = Ws[(kb + tig + 4) * 72 + n0 + g];
                #pragma unroll
                for (int mi = 0; mi < 4; mi++) mma8(acc[mi][nj], a[mi], b);
            }
        }
        __syncthreads();
    }

    #pragma unroll
    for (int mi = 0; mi < 4; mi++) {
        #pragma unroll
        for (int nj = 0; nj < 4; nj++) {
            int m0 = row0 + wm * 64 + mi * 16;
            int n0 = wn * 32 + nj * 8 + tig * 2;
            float* c = acc[mi][nj];
            *(float2*)&out[(size_t)(m0 + g) * H_ + n0]     = make_float2(c[0], c[1]);
            *(float2*)&out[(size_t)(m0 + g + 8) * H_ + n0] = make_float2(c[2], c[3]);
        }
    }
}

// ---------------------------------------------------------------------------
// Kernel 2: E = exp(Q@K^T / 32) lower tiles (zeros upper), rowsum atomics.
// grid=(16 s,32 t,8 b), block=128 (4 warps along s). Tile 64t x 128s.
// A-fragments via ldmatrix.x4.
// ---------------------------------------------------------------------------
#define SCORES_SMEM (64 * 68 * 4 + 128 * 68 * 4)   // 52224 B
__global__ __launch_bounds__(128, 4) void scores_kernel(float* __restrict__ attn) {
    const int s_t = blockIdx.x, t_t = blockIdx.y;
    const int b = blockIdx.z;
    const int t0 = t_t * 64, s0 = s_t * 128;
    const int tid = threadIdx.x;

    if (s0 > t0 + 63) {  // strictly-upper tile: zero fill
        #pragma unroll
        for (int it = 0; it < 16; it++) {
            int idx = tid + it * 128;       // 2048 quads = 64 x 32
            int r = idx >> 5, c4 = idx & 31;
            *(float4*)&attn[((size_t)b * T_ + t0 + r) * T_ + s0 + c4 * 4] =
                make_float4(0.f, 0.f, 0.f, 0.f);
        }
        return;
    }

    extern __shared__ unsigned smu[];
    unsigned* Qs = smu;            // [64][68]
    unsigned* Ks = smu + 64 * 68;  // [128][68]

    const float* q = g_q + (size_t)b * T_ * H_;
    const float* k = g_k + (size_t)b * T_ * H_;

    #pragma unroll
    for (int it = 0; it < 8; it++) {
        int idx = tid + it * 128;          // 1024 float4 = 64 x 16
        int r = idx >> 4, c4 = idx & 15;
        *(uint4*)&Qs[r * 68 + c4 * 4] =
            tf32x4(*(const float4*)&q[(size_t)(t0 + r) * H_ + c4 * 4]);
    }
    #pragma unroll
    for (int it = 0; it < 16; it++) {
        int idx = tid + it * 128;          // 2048 float4 = 128 x 16
        int r = idx >> 4, c4 = idx & 15;
        *(uint4*)&Ks[r * 68 + c4 * 4] =
            tf32x4(*(const float4*)&k[(size_t)(s0 + r) * H_ + c4 * 4]);
    }
    __syncthreads();

    const int warp = tid >> 5;
    const int lane = tid & 31;
    const int g    = lane >> 2;
    const int tig  = lane & 3;
    const unsigned qs_base = (unsigned)__cvta_generic_to_shared(Qs);
    const int lrow  = lane & 15;
    const int lkoff = (lane >> 4) * 4;

    float acc[4][4][4] = {};
    #pragma unroll
    for (int k8 = 0; k8 < 8; k8++) {
        const int kb = k8 * 8;
        unsigned a[4][4];
        #pragma unroll
        for (int mi = 0; mi < 4; mi++) {
            ldmA(a[mi], qs_base + (((mi * 16 + lrow) * 68 + kb + lkoff) << 2));
        }
        #pragma unroll
        for (int nj = 0; nj < 4; nj++) {
            int n0 = warp * 32 + nj * 8;
            unsigned bb[2];
            bb[0] = Ks[(n0 + g) * 68 + kb + tig];
            bb[1] = Ks[(n0 + g) * 68 + kb + tig + 4];
            #pragma unroll
            for (int mi = 0; mi < 4; mi++) mma8(acc[mi][nj], a[mi], bb);
        }
    }

    const float sc = 0.03125f;  // 1/sqrt(1024)
    const bool need_mask = (s0 + 127 > t0);
    #pragma unroll
    for (int mi = 0; mi < 4; mi++) {
        const int trow0 = t0 + mi * 16 + g;
        const int trow1 = trow0 + 8;
        float rs0 = 0.f, rs1 = 0.f;
        #pragma unroll
        for (int nj = 0; nj < 4; nj++) {
            int col = s0 + warp * 32 + nj * 8 + tig * 2;
            float* c = acc[mi][nj];
            float e0 = (!need_mask || col     <= trow0) ? __expf(c[0] * sc) : 0.f;
            float e1 = (!need_mask || col + 1 <= trow0) ? __expf(c[1] * sc) : 0.f;
            float e2 = (!need_mask || col     <= trow1) ? __expf(c[2] * sc) : 0.f;
            float e3 = (!need_mask || col + 1 <= trow1) ? __expf(c[3] * sc) : 0.f;
            rs0 += e0 + e1; rs1 += e2 + e3;
            *(float2*)&attn[((size_t)b * T_ + trow0) * T_ + col] = make_float2(e0, e1);
            *(float2*)&attn[((size_t)b * T_ + trow1) * T_ + col] = make_float2(e2, e3);
        }
        rs0 += __shfl_xor_sync(0xffffffffu, rs0, 1);
        rs0 += __shfl_xor_sync(0xffffffffu, rs0, 2);
        rs1 += __shfl_xor_sync(0xffffffffu, rs1, 1);
        rs1 += __shfl_xor_sync(0xffffffffu, rs1, 2);
        if (tig == 0) {
            atomicAdd(&g_rowsum[(size_t)b * T_ + trow0], rs0);
            atomicAdd(&g_rowsum[(size_t)b * T_ + trow1], rs1);
        }
    }
}

// ---------------------------------------------------------------------------
// Kernel 3: res += (attn/rowsum) @ V, split-K over 512-wide s-spans.
// Fused normalization. grid=(4 spans, 32 t desc, 8 b), block=128 (4 warps 2x2).
// Tile 64t x 64h. A-fragments via ldmatrix.x4.
// ---------------------------------------------------------------------------
#define AV_SMEM (64 * 68 * 4 + 64 * 72 * 4 + 64 * 4)   // 35904 B
__global__ __launch_bounds__(128, 5) void av_kernel(float* __restrict__ attn,
                                                    float* __restrict__ res) {
    const int sc   = blockIdx.x;
    const int t_t  = 31 - blockIdx.y;   // big tiles first
    const int b    = blockIdx.z;
    const int t0   = t_t * 64;
    if (sc * 512 > t0 + 63) return;

    extern __shared__ unsigned smu[];
    unsigned* As = smu;            // [64 t][68 s] tf32
    unsigned* Vs = smu + 64 * 68;  // [64 s][72 h] tf32
    float* sinv  = (float*)(smu + 64 * 68 + 64 * 72);

    const int tid = threadIdx.x;
    if (tid < 64) sinv[tid] = 1.f / g_rowsum[(size_t)b * T_ + t0 + tid];
    __syncthreads();

    const float* v = g_v + (size_t)b * T_ * H_;
    const int warp = tid >> 5;
    const int lane = tid & 31;
    const int g    = lane >> 2;
    const int tig  = lane & 3;
    const int wm   = warp >> 1;   // 0..1
    const int wn   = warp & 1;    // 0..1
    const unsigned as_base = (unsigned)__cvta_generic_to_shared(As);
    const int lrow  = lane & 15;
    const int lkoff = (lane >> 4) * 4;

    float acc[2][4][4] = {};

    #pragma unroll
    for (int c2 = 0; c2 < 8; c2++) {
        const int s0 = sc * 512 + c2 * 64;
        if (s0 > t0 + 63) break;

        #pragma unroll
        for (int it = 0; it < 8; it++) {
            int idx = tid + it * 128;          // 1024 float4 = 64 x 16
            int r = idx >> 4, c4 = idx & 15;
            float* ap = &attn[((size_t)b * T_ + t0 + r) * T_ + s0 + c4 * 4];
            float4 f = *(const float4*)ap;
            float iv = sinv[r];
            f = make_float4(f.x * iv, f.y * iv, f.z * iv, f.w * iv);
            *(float4*)ap = f;                  // normalized fp32 back to gmem
            *(uint4*)&As[r * 68 + c4 * 4] = tf32x4(f);
        }
        #pragma unroll
        for (int it = 0; it < 8; it++) {
            int idx = tid + it * 128;
            int r = idx >> 4, c4 = idx & 15;
            *(uint4*)&Vs[r * 72 + c4 * 4] =
                tf32x4(*(const float4*)&v[(size_t)(s0 + r) * H_ + c4 * 4]);
        }
        __syncthreads();

        #pragma unroll
        for (int k8 = 0; k8 < 8; k8++) {
            const int kb = k8 * 8;
            unsigned a[2][4];
            #pragma unroll
            for (int mi = 0; mi < 2; mi++) {
                int m0 = wm * 32 + mi * 16;
                ldmA(a[mi], as_base + (((m0 + lrow) * 68 + kb + lkoff) << 2));
            }
            #pragma unroll
            for (int nj = 0; nj < 4; nj++) {
                int n0 = wn * 32 + nj * 8;
                unsigned bb[2];
                bb[0] = Vs[(kb + tig) * 72 + n0 + g];
                bb[1] = Vs[(kb + tig + 4) * 72 + n0 + g];
                #pragma unroll
                for (int mi = 0; mi < 2; mi++) mma8(acc[mi][nj], a[mi], bb);
            }
        }
        __syncthreads();
    }

    #pragma unroll
    for (int mi = 0; mi < 2; mi++) {
        #pragma unroll
        for (int nj = 0; nj < 4; nj++) {
            int m0 = t0 + wm * 32 + mi * 16;
            int n0 = wn * 32 + nj * 8 + tig * 2;
            float* c = acc[mi][nj];
            size_t r0 = ((size_t)b * T_ + m0 + g) * H_ + n0;
            size_t r1 = ((size_t)b * T_ + m0 + g + 8) * H_ + n0;
            atomicAdd(&res[r0],     c[0]);
            atomicAdd(&res[r0 + 1], c[1]);
            atomicAdd(&res[r1],     c[2]);
            atomicAdd(&res[r1 + 1], c[3]);
        }
    }
}

// ---------------------------------------------------------------------------
extern "C" void kernel_launch(void* const* d_in, const int* in_sizes, int n_in,
                              void* d_out, int out_size) {
    (void)in_sizes; (void)n_in;
    const float* x  = (const float*)d_in[0];
    const float* Wq = (const float*)d_in[1];
    const float* Wk = (const float*)d_in[2];
    const float* Wv = (const float*)d_in[3];

    const size_t n_res  = (size_t)B_ * T_ * H_;
    const size_t n_attn = (size_t)B_ * T_ * T_;

    float* attn_scratch = nullptr;
    float* res_scratch = nullptr;
    float* rowsum = nullptr;
    cudaGetSymbolAddress((void**)&attn_scratch, g_attn_scratch);
    cudaGetSymbolAddress((void**)&res_scratch, g_res);
    cudaGetSymbolAddress((void**)&rowsum, g_rowsum);

    float* res;
    float* attn;
    if ((size_t)out_size == n_res + n_attn) {
        res  = (float*)d_out;
        attn = (float*)d_out + n_res;
    } else if ((size_t)out_size == n_attn) {
        attn = (float*)d_out;
        res  = res_scratch;
    } else {
        res  = (float*)d_out;
        attn = attn_scratch;
    }

    cudaFuncSetAttribute(proj_kernel,   cudaFuncAttributeMaxDynamicSharedMemorySize, PROJ_SMEM);
    cudaFuncSetAttribute(scores_kernel, cudaFuncAttributeMaxDynamicSharedMemorySize, SCORES_SMEM);
    cudaFuncSetAttribute(av_kernel,     cudaFuncAttributeMaxDynamicSharedMemorySize, AV_SMEM);

    cudaMemsetAsync(rowsum, 0, NROWS * sizeof(float));
    cudaMemsetAsync(res, 0, n_res * sizeof(float));
    proj_kernel<<<dim3(128, 3), 128, PROJ_SMEM>>>(x, Wq, Wk, Wv);
    scores_kernel<<<dim3(16, 32, 8), 128, SCORES_SMEM>>>(attn);
    av_kernel<<<dim3(4, 32, 8), 128, AV_SMEM>>>(attn, res);
}

// round 13
// speedup vs baseline: 1.6009x; 1.0385x over previous
#include <cuda_runtime.h>
#include <math.h>

#define B_ 8
#define T_ 2048
#define C_ 1024
#define H_ 64
#define NROWS (B_ * T_)   // 16384

__device__ float g_q[NROWS * H_];
__device__ float g_k[NROWS * H_];
__device__ float g_v[NROWS * H_];
__device__ float g_res[NROWS * H_];
__device__ float g_rowsum[NROWS];
__device__ float g_attn_scratch[(size_t)B_ * T_ * T_];

// ---- tf32 helpers -----------------------------------------------------------
__device__ __forceinline__ unsigned tf32(float f) {
    unsigned r;
    asm("cvt.rna.tf32.f32 %0, %1;" : "=r"(r) : "f"(f));
    return r;
}
__device__ __forceinline__ uint4 tf32x4(float4 f) {
    uint4 u;
    u.x = tf32(f.x); u.y = tf32(f.y); u.z = tf32(f.z); u.w = tf32(f.w);
    return u;
}
// D += A(16x8,row) * B(8x8,col); tf32 in, fp32 accum
__device__ __forceinline__ void mma8(float* c, const unsigned* a, const unsigned* b) {
    asm("mma.sync.aligned.m16n8k8.row.col.f32.tf32.tf32.f32 "
        "{%0,%1,%2,%3},{%4,%5,%6,%7},{%8,%9},{%0,%1,%2,%3};"
        : "+f"(c[0]), "+f"(c[1]), "+f"(c[2]), "+f"(c[3])
        : "r"(a[0]), "r"(a[1]), "r"(a[2]), "r"(a[3]), "r"(b[0]), "r"(b[1]));
}
// Load a full 16x8 A-fragment (raw 32-bit words) in one instruction.
__device__ __forceinline__ void ldmA(unsigned* a, unsigned saddr) {
    asm volatile("ldmatrix.sync.aligned.m8n8.x4.shared.b16 {%0,%1,%2,%3}, [%4];"
        : "=r"(a[0]), "=r"(a[1]), "=r"(a[2]), "=r"(a[3]) : "r"(saddr));
}
__device__ __forceinline__ unsigned tf32u(unsigned raw) {   // raw fp32 bits -> tf32 (rna)
    unsigned r;
    asm("cvt.rna.tf32.f32 %0, %1;" : "=r"(r) : "f"(__uint_as_float(raw)));
    return r;
}

#define CP_ASYNC16(dst, src) \
    asm volatile("cp.async.cg.shared.global [%0], [%1], 16;" :: "r"(dst), "l"(src))
#define CP_COMMIT()  asm volatile("cp.async.commit_group;")
#define CP_WAIT1()   asm volatile("cp.async.wait_group 1;" ::: "memory")

// ---------------------------------------------------------------------------
// Kernel 1: QKV projection, cp.async double-buffered, FULL 64-wide K chunks.
// grid=(128, 3), block=128 (4 warps: 2m x 2n). Block tile 128m x 64h.
// Warp tile 64m x 32h (mi=4, nj=4). A via ldmatrix + cvt, B via LDS + cvt.
// smem: 2 x (X[128][68] + W[64][72]) raw fp32 = 106496 B -> 2 CTAs/SM.
// ---------------------------------------------------------------------------
#define XST (128 * 68)
#define WST (64 * 72)
#define PROJ_SMEM ((2 * XST + 2 * WST) * 4)   // 106496 B
__global__ __launch_bounds__(128) void proj_kernel(const float* __restrict__ x,
                                                   const float* __restrict__ Wq,
                                                   const float* __restrict__ Wk,
                                                   const float* __restrict__ Wv) {
    extern __shared__ float smf[];
    float* Xs[2] = { smf, smf + XST };
    float* Ws[2] = { smf + 2 * XST, smf + 2 * XST + WST };

    const float* W; float* out;
    if (blockIdx.y == 0)      { W = Wq; out = g_q; }
    else if (blockIdx.y == 1) { W = Wk; out = g_k; }
    else                      { W = Wv; out = g_v; }

    const int row0 = blockIdx.x * 128;
    const int tid  = threadIdx.x;
    const int warp = tid >> 5;
    const int lane = tid & 31;
    const int g    = lane >> 2;    // 0..7
    const int tig  = lane & 3;     // 0..3
    const int wm   = warp >> 1;    // 0..1 (m)
    const int wn   = warp & 1;     // 0..1 (n)

    // loader geometry: r0 = tid>>4 (row within tile step), c4 = tid&15
    const int r0 = tid >> 4;
    const int c4 = tid & 15;
    const float* px = x + (size_t)(row0 + r0) * C_ + c4 * 4;  // + it*8*C_ + c*64
    const float* pw = W + (size_t)r0 * H_ + c4 * 4;           // + it*8*H_ + c*64*H_
    unsigned xd[2], wd[2];
    #pragma unroll
    for (int b = 0; b < 2; b++) {
        xd[b] = (unsigned)__cvta_generic_to_shared(&Xs[b][r0 * 68 + c4 * 4]);
        wd[b] = (unsigned)__cvta_generic_to_shared(&Ws[b][r0 * 72 + c4 * 4]);
    }

    const unsigned xs_base[2] = {
        (unsigned)__cvta_generic_to_shared(Xs[0]),
        (unsigned)__cvta_generic_to_shared(Xs[1]) };
    const int lrow  = lane & 15;
    const int lkoff = (lane >> 4) * 4;

    float acc[4][4][4] = {};

    // prologue: chunk 0 -> stage 0
    #pragma unroll
    for (int it = 0; it < 16; it++) CP_ASYNC16(xd[0] + it * 8 * 68 * 4, px + it * 8 * C_);
    #pragma unroll
    for (int it = 0; it < 8; it++)  CP_ASYNC16(wd[0] + it * 8 * 72 * 4, pw + it * 8 * H_);
    CP_COMMIT();

    for (int c = 0; c < 16; c++) {
        const int b = c & 1, nb = b ^ 1;
        if (c < 15) {
            const float* pxc = px + (c + 1) * 64;
            const float* pwc = pw + (size_t)(c + 1) * 64 * H_;
            #pragma unroll
            for (int it = 0; it < 16; it++)
                CP_ASYNC16(xd[nb] + it * 8 * 68 * 4, pxc + it * 8 * C_);
            #pragma unroll
            for (int it = 0; it < 8; it++)
                CP_ASYNC16(wd[nb] + it * 8 * 72 * 4, pwc + it * 8 * H_);
        }
        CP_COMMIT();
        CP_WAIT1();
        __syncthreads();

        const float* Wf = Ws[b];
        #pragma unroll
        for (int k8 = 0; k8 < 8; k8++) {
            const int kb = k8 * 8;
            unsigned a[4][4];
            #pragma unroll
            for (int mi = 0; mi < 4; mi++) {
                int m0 = wm * 64 + mi * 16;
                ldmA(a[mi], xs_base[b] + (((m0 + lrow) * 68 + kb + lkoff) << 2));
                a[mi][0] = tf32u(a[mi][0]); a[mi][1] = tf32u(a[mi][1]);
                a[mi][2] = tf32u(a[mi][2]); a[mi][3] = tf32u(a[mi][3]);
            }
            #pragma unroll
            for (int nj = 0; nj < 4; nj++) {
                int n0 = wn * 32 + nj * 8;
                unsigned bb[2];
                bb[0] = tf32(Wf[(kb + tig) * 72 + n0 + g]);
                bb[1] = tf32(Wf[(kb + tig + 4) * 72 + n0 + g]);
                #pragma unroll
                for (int mi = 0; mi < 4; mi++) mma8(acc[mi][nj], a[mi], bb);
            }
        }
        __syncthreads();
    }

    #pragma unroll
    for (int mi = 0; mi < 4; mi++) {
        #pragma unroll
        for (int nj = 0; nj < 4; nj++) {
            int m0 = row0 + wm * 64 + mi * 16;
            int n0 = wn * 32 + nj * 8 + tig * 2;
            float* c = acc[mi][nj];
            *(float2*)&out[(size_t)(m0 + g) * H_ + n0]     = make_float2(c[0], c[1]);
            *(float2*)&out[(size_t)(m0 + g + 8) * H_ + n0] = make_float2(c[2], c[3]);
        }
    }
}

// ---------------------------------------------------------------------------
// Kernel 2: E = exp(Q@K^T / 32) lower tiles (zeros upper), rowsum atomics.
// grid=(16 s,32 t,8 b), block=128. Tile 64t x 128s. (known-good)
// ---------------------------------------------------------------------------
#define SCORES_SMEM (64 * 68 * 4 + 128 * 68 * 4)   // 52224 B
__global__ __launch_bounds__(128, 4) void scores_kernel(float* __restrict__ attn) {
    const int s_t = blockIdx.x, t_t = blockIdx.y;
    const int b = blockIdx.z;
    const int t0 = t_t * 64, s0 = s_t * 128;
    const int tid = threadIdx.x;

    if (s0 > t0 + 63) {  // strictly-upper tile: zero fill
        #pragma unroll
        for (int it = 0; it < 16; it++) {
            int idx = tid + it * 128;       // 2048 quads = 64 x 32
            int r = idx >> 5, c4 = idx & 31;
            *(float4*)&attn[((size_t)b * T_ + t0 + r) * T_ + s0 + c4 * 4] =
                make_float4(0.f, 0.f, 0.f, 0.f);
        }
        return;
    }

    extern __shared__ unsigned smu[];
    unsigned* Qs = smu;            // [64][68]
    unsigned* Ks = smu + 64 * 68;  // [128][68]

    const float* q = g_q + (size_t)b * T_ * H_;
    const float* k = g_k + (size_t)b * T_ * H_;

    #pragma unroll
    for (int it = 0; it < 8; it++) {
        int idx = tid + it * 128;
        int r = idx >> 4, c4 = idx & 15;
        *(uint4*)&Qs[r * 68 + c4 * 4] =
            tf32x4(*(const float4*)&q[(size_t)(t0 + r) * H_ + c4 * 4]);
    }
    #pragma unroll
    for (int it = 0; it < 16; it++) {
        int idx = tid + it * 128;
        int r = idx >> 4, c4 = idx & 15;
        *(uint4*)&Ks[r * 68 + c4 * 4] =
            tf32x4(*(const float4*)&k[(size_t)(s0 + r) * H_ + c4 * 4]);
    }
    __syncthreads();

    const int warp = tid >> 5;
    const int lane = tid & 31;
    const int g    = lane >> 2;
    const int tig  = lane & 3;
    const unsigned qs_base = (unsigned)__cvta_generic_to_shared(Qs);
    const int lrow  = lane & 15;
    const int lkoff = (lane >> 4) * 4;

    float acc[4][4][4] = {};
    #pragma unroll
    for (int k8 = 0; k8 < 8; k8++) {
        const int kb = k8 * 8;
        unsigned a[4][4];
        #pragma unroll
        for (int mi = 0; mi < 4; mi++) {
            ldmA(a[mi], qs_base + (((mi * 16 + lrow) * 68 + kb + lkoff) << 2));
        }
        #pragma unroll
        for (int nj = 0; nj < 4; nj++) {
            int n0 = warp * 32 + nj * 8;
            unsigned bb[2];
            bb[0] = Ks[(n0 + g) * 68 + kb + tig];
            bb[1] = Ks[(n0 + g) * 68 + kb + tig + 4];
            #pragma unroll
            for (int mi = 0; mi < 4; mi++) mma8(acc[mi][nj], a[mi], bb);
        }
    }

    const float sc = 0.03125f;  // 1/sqrt(1024)
    const bool need_mask = (s0 + 127 > t0);
    #pragma unroll
    for (int mi = 0; mi < 4; mi++) {
        const int trow0 = t0 + mi * 16 + g;
        const int trow1 = trow0 + 8;
        float rs0 = 0.f, rs1 = 0.f;
        #pragma unroll
        for (int nj = 0; nj < 4; nj++) {
            int col = s0 + warp * 32 + nj * 8 + tig * 2;
            float* c = acc[mi][nj];
            float e0 = (!need_mask || col     <= trow0) ? __expf(c[0] * sc) : 0.f;
            float e1 = (!need_mask || col + 1 <= trow0) ? __expf(c[1] * sc) : 0.f;
            float e2 = (!need_mask || col     <= trow1) ? __expf(c[2] * sc) : 0.f;
            float e3 = (!need_mask || col + 1 <= trow1) ? __expf(c[3] * sc) : 0.f;
            rs0 += e0 + e1; rs1 += e2 + e3;
            *(float2*)&attn[((size_t)b * T_ + trow0) * T_ + col] = make_float2(e0, e1);
            *(float2*)&attn[((size_t)b * T_ + trow1) * T_ + col] = make_float2(e2, e3);
        }
        rs0 += __shfl_xor_sync(0xffffffffu, rs0, 1);
        rs0 += __shfl_xor_sync(0xffffffffu, rs0, 2);
        rs1 += __shfl_xor_sync(0xffffffffu, rs1, 1);
        rs1 += __shfl_xor_sync(0xffffffffu, rs1, 2);
        if (tig == 0) {
            atomicAdd(&g_rowsum[(size_t)b * T_ + trow0], rs0);
            atomicAdd(&g_rowsum[(size_t)b * T_ + trow1], rs1);
        }
    }
}

// ---------------------------------------------------------------------------
// Kernel 3: res += (attn/rowsum) @ V, split-K over 256-wide s-spans.
// Fused normalization. grid=(8 spans, 32 t desc, 8 b), block=128 (4 warps 2x2).
// Tile 64t x 64h. Better balance: 1152 work CTAs, <=4 chunks each.
// ---------------------------------------------------------------------------
#define AV_SMEM (64 * 68 * 4 + 64 * 72 * 4 + 64 * 4)   // 35904 B
__global__ __launch_bounds__(128, 5) void av_kernel(float* __restrict__ attn,
                                                    float* __restrict__ res) {
    const int sc   = blockIdx.x;
    const int t_t  = 31 - blockIdx.y;   // big tiles first
    const int b    = blockIdx.z;
    const int t0   = t_t * 64;
    if (sc * 256 > t0 + 63) return;

    extern __shared__ unsigned smu[];
    unsigned* As = smu;            // [64 t][68 s] tf32
    unsigned* Vs = smu + 64 * 68;  // [64 s][72 h] tf32
    float* sinv  = (float*)(smu + 64 * 68 + 64 * 72);

    const int tid = threadIdx.x;
    if (tid < 64) sinv[tid] = 1.f / g_rowsum[(size_t)b * T_ + t0 + tid];
    __syncthreads();

    const float* v = g_v + (size_t)b * T_ * H_;
    const int warp = tid >> 5;
    const int lane = tid & 31;
    const int g    = lane >> 2;
    const int tig  = lane & 3;
    const int wm   = warp >> 1;   // 0..1
    const int wn   = warp & 1;    // 0..1
    const unsigned as_base = (unsigned)__cvta_generic_to_shared(As);
    const int lrow  = lane & 15;
    const int lkoff = (lane >> 4) * 4;

    float acc[2][4][4] = {};

    #pragma unroll
    for (int c2 = 0; c2 < 4; c2++) {
        const int s0 = sc * 256 + c2 * 64;
        if (s0 > t0 + 63) break;

        #pragma unroll
        for (int it = 0; it < 8; it++) {
            int idx = tid + it * 128;
            int r = idx >> 4, c4 = idx & 15;
            float* ap = &attn[((size_t)b * T_ + t0 + r) * T_ + s0 + c4 * 4];
            float4 f = *(const float4*)ap;
            float iv = sinv[r];
            f = make_float4(f.x * iv, f.y * iv, f.z * iv, f.w * iv);
            *(float4*)ap = f;                  // normalized fp32 back to gmem
            *(uint4*)&As[r * 68 + c4 * 4] = tf32x4(f);
        }
        #pragma unroll
        for (int it = 0; it < 8; it++) {
            int idx = tid + it * 128;
            int r = idx >> 4, c4 = idx & 15;
            *(uint4*)&Vs[r * 72 + c4 * 4] =
                tf32x4(*(const float4*)&v[(size_t)(s0 + r) * H_ + c4 * 4]);
        }
        __syncthreads();

        #pragma unroll
        for (int k8 = 0; k8 < 8; k8++) {
            const int kb = k8 * 8;
            unsigned a[2][4];
            #pragma unroll
            for (int mi = 0; mi < 2; mi++) {
                int m0 = wm * 32 + mi * 16;
                ldmA(a[mi], as_base + (((m0 + lrow) * 68 + kb + lkoff) << 2));
            }
            #pragma unroll
            for (int nj = 0; nj < 4; nj++) {
                int n0 = wn * 32 + nj * 8;
                unsigned bb[2];
                bb[0] = Vs[(kb + tig) * 72 + n0 + g];
                bb[1] = Vs[(kb + tig + 4) * 72 + n0 + g];
                #pragma unroll
                for (int mi = 0; mi < 2; mi++) mma8(acc[mi][nj], a[mi], bb);
            }
        }
        __syncthreads();
    }

    #pragma unroll
    for (int mi = 0; mi < 2; mi++) {
        #pragma unroll
        for (int nj = 0; nj < 4; nj++) {
            int m0 = t0 + wm * 32 + mi * 16;
            int n0 = wn * 32 + nj * 8 + tig * 2;
            float* c = acc[mi][nj];
            size_t r0 = ((size_t)b * T_ + m0 + g) * H_ + n0;
            size_t r1 = ((size_t)b * T_ + m0 + g + 8) * H_ + n0;
            atomicAdd(&res[r0],     c[0]);
            atomicAdd(&res[r0 + 1], c[1]);
            atomicAdd(&res[r1],     c[2]);
            atomicAdd(&res[r1 + 1], c[3]);
        }
    }
}

// ---------------------------------------------------------------------------
extern "C" void kernel_launch(void* const* d_in, const int* in_sizes, int n_in,
                              void* d_out, int out_size) {
    (void)in_sizes; (void)n_in;
    const float* x  = (const float*)d_in[0];
    const float* Wq = (const float*)d_in[1];
    const float* Wk = (const float*)d_in[2];
    const float* Wv = (const float*)d_in[3];

    const size_t n_res  = (size_t)B_ * T_ * H_;
    const size_t n_attn = (size_t)B_ * T_ * T_;

    float* attn_scratch = nullptr;
    float* res_scratch = nullptr;
    float* rowsum = nullptr;
    cudaGetSymbolAddress((void**)&attn_scratch, g_attn_scratch);
    cudaGetSymbolAddress((void**)&res_scratch, g_res);
    cudaGetSymbolAddress((void**)&rowsum, g_rowsum);

    float* res;
    float* attn;
    if ((size_t)out_size == n_res + n_attn) {
        res  = (float*)d_out;
        attn = (float*)d_out + n_res;
    } else if ((size_t)out_size == n_attn) {
        attn = (float*)d_out;
        res  = res_scratch;
    } else {
        res  = (float*)d_out;
        attn = attn_scratch;
    }

    cudaFuncSetAttribute(proj_kernel,   cudaFuncAttributeMaxDynamicSharedMemorySize, PROJ_SMEM);
    cudaFuncSetAttribute(scores_kernel, cudaFuncAttributeMaxDynamicSharedMemorySize, SCORES_SMEM);
    cudaFuncSetAttribute(av_kernel,     cudaFuncAttributeMaxDynamicSharedMemorySize, AV_SMEM);

    cudaMemsetAsync(rowsum, 0, NROWS * sizeof(float));
    cudaMemsetAsync(res, 0, n_res * sizeof(float));
    proj_kernel<<<dim3(128, 3), 128, PROJ_SMEM>>>(x, Wq, Wk, Wv);
    scores_kernel<<<dim3(16, 32, 8), 128, SCORES_SMEM>>>(attn);
    av_kernel<<<dim3(8, 32, 8), 128, AV_SMEM>>>(attn, res);
}

// round 14
// speedup vs baseline: 1.6259x; 1.0156x over previous
#include <cuda_runtime.h>
#include <math.h>

#define B_ 8
#define T_ 2048
#define C_ 1024
#define H_ 64
#define NROWS (B_ * T_)   // 16384

__device__ float g_q[NROWS * H_];
__device__ float g_k[NROWS * H_];
__device__ float g_v[NROWS * H_];
__device__ float g_res[NROWS * H_];
__device__ float g_rowsum[NROWS];
__device__ float g_attn_scratch[(size_t)B_ * T_ * T_];

// ---- tf32 helpers -----------------------------------------------------------
__device__ __forceinline__ unsigned tf32(float f) {
    unsigned r;
    asm("cvt.rna.tf32.f32 %0, %1;" : "=r"(r) : "f"(f));
    return r;
}
__device__ __forceinline__ uint4 tf32x4(float4 f) {
    uint4 u;
    u.x = tf32(f.x); u.y = tf32(f.y); u.z = tf32(f.z); u.w = tf32(f.w);
    return u;
}
// D += A(16x8,row) * B(8x8,col); tf32 in, fp32 accum
__device__ __forceinline__ void mma8(float* c, const unsigned* a, const unsigned* b) {
    asm("mma.sync.aligned.m16n8k8.row.col.f32.tf32.tf32.f32 "
        "{%0,%1,%2,%3},{%4,%5,%6,%7},{%8,%9},{%0,%1,%2,%3};"
        : "+f"(c[0]), "+f"(c[1]), "+f"(c[2]), "+f"(c[3])
        : "r"(a[0]), "r"(a[1]), "r"(a[2]), "r"(a[3]), "r"(b[0]), "r"(b[1]));
}
// Load a full 16x8 tf32 A-fragment in one instruction.
__device__ __forceinline__ void ldmA(unsigned* a, unsigned saddr) {
    asm volatile("ldmatrix.sync.aligned.m8n8.x4.shared.b16 {%0,%1,%2,%3}, [%4];"
        : "=r"(a[0]), "=r"(a[1]), "=r"(a[2]), "=r"(a[3]) : "r"(saddr));
}

// ---------------------------------------------------------------------------
// Kernel 1: QKV projection (round-12 version, 61.4us measured).
// grid=(128, 3), block=128 (4 warps: 2m x 2n). Block tile 128m x 64h.
// Warp tile 64m x 32h (mi=4, nj=4). A-fragments via ldmatrix.x4.
// ---------------------------------------------------------------------------
#define PROJ_SMEM (128 * 68 * 4 + 64 * 72 * 4)   // 53248 B
__global__ __launch_bounds__(128) void proj_kernel(const float* __restrict__ x,
                                                   const float* __restrict__ Wq,
                                                   const float* __restrict__ Wk,
                                                   const float* __restrict__ Wv) {
    extern __shared__ unsigned smu[];
    unsigned* Xs = smu;             // [128][68]
    unsigned* Ws = smu + 128 * 68;  // [64][72]

    const float* W; float* out;
    if (blockIdx.y == 0)      { W = Wq; out = g_q; }
    else if (blockIdx.y == 1) { W = Wk; out = g_k; }
    else                      { W = Wv; out = g_v; }

    const int row0 = blockIdx.x * 128;
    const int tid  = threadIdx.x;
    const int warp = tid >> 5;
    const int lane = tid & 31;
    const int g    = lane >> 2;    // 0..7
    const int tig  = lane & 3;     // 0..3
    const int wm   = warp >> 1;    // 0..1 (m)
    const int wn   = warp & 1;     // 0..1 (n)

    const unsigned xs_base = (unsigned)__cvta_generic_to_shared(Xs);
    const int lrow  = lane & 15;
    const int lkoff = (lane >> 4) * 4;

    float acc[4][4][4] = {};

    for (int k0 = 0; k0 < C_; k0 += 64) {
        #pragma unroll
        for (int it = 0; it < 16; it++) {
            int idx = tid + it * 128;         // 2048 float4 = 128 x 16
            int r = idx >> 4, c4 = idx & 15;
            *(uint4*)&Xs[r * 68 + c4 * 4] =
                tf32x4(*(const float4*)&x[(size_t)(row0 + r) * C_ + k0 + c4 * 4]);
        }
        #pragma unroll
        for (int it = 0; it < 8; it++) {
            int idx = tid + it * 128;         // 1024 float4 = 64 x 16
            int r = idx >> 4, c4 = idx & 15;
            *(uint4*)&Ws[r * 72 + c4 * 4] =
                tf32x4(*(const float4*)&W[(size_t)(k0 + r) * H_ + c4 * 4]);
        }
        __syncthreads();

        #pragma unroll
        for (int k8 = 0; k8 < 8; k8++) {
            const int kb = k8 * 8;
            unsigned a[4][4];
            #pragma unroll
            for (int mi = 0; mi < 4; mi++) {
                int m0 = wm * 64 + mi * 16;
                ldmA(a[mi], xs_base + (((m0 + lrow) * 68 + kb + lkoff) << 2));
            }
            #pragma unroll
            for (int nj = 0; nj < 4; nj++) {
                int n0 = wn * 32 + nj * 8;
                unsigned b[2];
                b[0] = Ws[(kb + tig) * 72 + n0 + g];
                b[1] = Ws[(kb + tig + 4) * 72 + n0 + g];
                #pragma unroll
                for (int mi = 0; mi < 4; mi++) mma8(acc[mi][nj], a[mi], b);
            }
        }
        __syncthreads();
    }

    #pragma unroll
    for (int mi = 0; mi < 4; mi++) {
        #pragma unroll
        for (int nj = 0; nj < 4; nj++) {
            int m0 = row0 + wm * 64 + mi * 16;
            int n0 = wn * 32 + nj * 8 + tig * 2;
            float* c = acc[mi][nj];
            *(float2*)&out[(size_t)(m0 + g) * H_ + n0]     = make_float2(c[0], c[1]);
            *(float2*)&out[(size_t)(m0 + g + 8) * H_ + n0] = make_float2(c[2], c[3]);
        }
    }
}

// ---------------------------------------------------------------------------
// Kernel 2: E = exp(Q@K^T / 32) lower tiles (zeros upper), rowsum atomics.
// grid=(16 s,32 t,8 b), block=128. Tile 64t x 128s. (known-good)
// ---------------------------------------------------------------------------
#define SCORES_SMEM (64 * 68 * 4 + 128 * 68 * 4)   // 52224 B
__global__ __launch_bounds__(128, 4) void scores_kernel(float* __restrict__ attn) {
    const int s_t = blockIdx.x, t_t = blockIdx.y;
    const int b = blockIdx.z;
    const int t0 = t_t * 64, s0 = s_t * 128;
    const int tid = threadIdx.x;

    if (s0 > t0 + 63) {  // strictly-upper tile: zero fill
        #pragma unroll
        for (int it = 0; it < 16; it++) {
            int idx = tid + it * 128;       // 2048 quads = 64 x 32
            int r = idx >> 5, c4 = idx & 31;
            *(float4*)&attn[((size_t)b * T_ + t0 + r) * T_ + s0 + c4 * 4] =
                make_float4(0.f, 0.f, 0.f, 0.f);
        }
        return;
    }

    extern __shared__ unsigned smu[];
    unsigned* Qs = smu;            // [64][68]
    unsigned* Ks = smu + 64 * 68;  // [128][68]

    const float* q = g_q + (size_t)b * T_ * H_;
    const float* k = g_k + (size_t)b * T_ * H_;

    #pragma unroll
    for (int it = 0; it < 8; it++) {
        int idx = tid + it * 128;
        int r = idx >> 4, c4 = idx & 15;
        *(uint4*)&Qs[r * 68 + c4 * 4] =
            tf32x4(*(const float4*)&q[(size_t)(t0 + r) * H_ + c4 * 4]);
    }
    #pragma unroll
    for (int it = 0; it < 16; it++) {
        int idx = tid + it * 128;
        int r = idx >> 4, c4 = idx & 15;
        *(uint4*)&Ks[r * 68 + c4 * 4] =
            tf32x4(*(const float4*)&k[(size_t)(s0 + r) * H_ + c4 * 4]);
    }
    __syncthreads();

    const int warp = tid >> 5;
    const int lane = tid & 31;
    const int g    = lane >> 2;
    const int tig  = lane & 3;
    const unsigned qs_base = (unsigned)__cvta_generic_to_shared(Qs);
    const int lrow  = lane & 15;
    const int lkoff = (lane >> 4) * 4;

    float acc[4][4][4] = {};
    #pragma unroll
    for (int k8 = 0; k8 < 8; k8++) {
        const int kb = k8 * 8;
        unsigned a[4][4];
        #pragma unroll
        for (int mi = 0; mi < 4; mi++) {
            ldmA(a[mi], qs_base + (((mi * 16 + lrow) * 68 + kb + lkoff) << 2));
        }
        #pragma unroll
        for (int nj = 0; nj < 4; nj++) {
            int n0 = warp * 32 + nj * 8;
            unsigned bb[2];
            bb[0] = Ks[(n0 + g) * 68 + kb + tig];
            bb[1] = Ks[(n0 + g) * 68 + kb + tig + 4];
            #pragma unroll
            for (int mi = 0; mi < 4; mi++) mma8(acc[mi][nj], a[mi], bb);
        }
    }

    const float sc = 0.03125f;  // 1/sqrt(1024)
    const bool need_mask = (s0 + 127 > t0);
    #pragma unroll
    for (int mi = 0; mi < 4; mi++) {
        const int trow0 = t0 + mi * 16 + g;
        const int trow1 = trow0 + 8;
        float rs0 = 0.f, rs1 = 0.f;
        #pragma unroll
        for (int nj = 0; nj < 4; nj++) {
            int col = s0 + warp * 32 + nj * 8 + tig * 2;
            float* c = acc[mi][nj];
            float e0 = (!need_mask || col     <= trow0) ? __expf(c[0] * sc) : 0.f;
            float e1 = (!need_mask || col + 1 <= trow0) ? __expf(c[1] * sc) : 0.f;
            float e2 = (!need_mask || col     <= trow1) ? __expf(c[2] * sc) : 0.f;
            float e3 = (!need_mask || col + 1 <= trow1) ? __expf(c[3] * sc) : 0.f;
            rs0 += e0 + e1; rs1 += e2 + e3;
            *(float2*)&attn[((size_t)b * T_ + trow0) * T_ + col] = make_float2(e0, e1);
            *(float2*)&attn[((size_t)b * T_ + trow1) * T_ + col] = make_float2(e2, e3);
        }
        rs0 += __shfl_xor_sync(0xffffffffu, rs0, 1);
        rs0 += __shfl_xor_sync(0xffffffffu, rs0, 2);
        rs1 += __shfl_xor_sync(0xffffffffu, rs1, 1);
        rs1 += __shfl_xor_sync(0xffffffffu, rs1, 2);
        if (tig == 0) {
            atomicAdd(&g_rowsum[(size_t)b * T_ + trow0], rs0);
            atomicAdd(&g_rowsum[(size_t)b * T_ + trow1], rs1);
        }
    }
}

// ---------------------------------------------------------------------------
// Kernel 3: res += (attn/rowsum) @ V, split-K over 256-wide s-spans.
// Fused normalization. grid=(8 spans, 32 t desc, 8 b), block=128 (4 warps 2x2).
// Tile 64t x 64h. (round-13 version, known-good)
// ---------------------------------------------------------------------------
#define AV_SMEM (64 * 68 * 4 + 64 * 72 * 4 + 64 * 4)   // 35904 B
__global__ __launch_bounds__(128, 5) void av_kernel(float* __restrict__ attn,
                                                    float* __restrict__ res) {
    const int sc   = blockIdx.x;
    const int t_t  = 31 - blockIdx.y;   // big tiles first
    const int b    = blockIdx.z;
    const int t0   = t_t * 64;
    if (sc * 256 > t0 + 63) return;

    extern __shared__ unsigned smu[];
    unsigned* As = smu;            // [64 t][68 s] tf32
    unsigned* Vs = smu + 64 * 68;  // [64 s][72 h] tf32
    float* sinv  = (float*)(smu + 64 * 68 + 64 * 72);

    const int tid = threadIdx.x;
    if (tid < 64) sinv[tid] = 1.f / g_rowsum[(size_t)b * T_ + t0 + tid];
    __syncthreads();

    const float* v = g_v + (size_t)b * T_ * H_;
    const int warp = tid >> 5;
    const int lane = tid & 31;
    const int g    = lane >> 2;
    const int tig  = lane & 3;
    const int wm   = warp >> 1;   // 0..1
    const int wn   = warp & 1;    // 0..1
    const unsigned as_base = (unsigned)__cvta_generic_to_shared(As);
    const int lrow  = lane & 15;
    const int lkoff = (lane >> 4) * 4;

    float acc[2][4][4] = {};

    #pragma unroll
    for (int c2 = 0; c2 < 4; c2++) {
        const int s0 = sc * 256 + c2 * 64;
        if (s0 > t0 + 63) break;

        #pragma unroll
        for (int it = 0; it < 8; it++) {
            int idx = tid + it * 128;
            int r = idx >> 4, c4 = idx & 15;
            float* ap = &attn[((size_t)b * T_ + t0 + r) * T_ + s0 + c4 * 4];
            float4 f = *(const float4*)ap;
            float iv = sinv[r];
            f = make_float4(f.x * iv, f.y * iv, f.z * iv, f.w * iv);
            *(float4*)ap = f;                  // normalized fp32 back to gmem
            *(uint4*)&As[r * 68 + c4 * 4] = tf32x4(f);
        }
        #pragma unroll
        for (int it = 0; it < 8; it++) {
            int idx = tid + it * 128;
            int r = idx >> 4, c4 = idx & 15;
            *(uint4*)&Vs[r * 72 + c4 * 4] =
                tf32x4(*(const float4*)&v[(size_t)(s0 + r) * H_ + c4 * 4]);
        }
        __syncthreads();

        #pragma unroll
        for (int k8 = 0; k8 < 8; k8++) {
            const int kb = k8 * 8;
            unsigned a[2][4];
            #pragma unroll
            for (int mi = 0; mi < 2; mi++) {
                int m0 = wm * 32 + mi * 16;
                ldmA(a[mi], as_base + (((m0 + lrow) * 68 + kb + lkoff) << 2));
            }
            #pragma unroll
            for (int nj = 0; nj < 4; nj++) {
                int n0 = wn * 32 + nj * 8;
                unsigned bb[2];
                bb[0] = Vs[(kb + tig) * 72 + n0 + g];
                bb[1] = Vs[(kb + tig + 4) * 72 + n0 + g];
                #pragma unroll
                for (int mi = 0; mi < 2; mi++) mma8(acc[mi][nj], a[mi], bb);
            }
        }
        __syncthreads();
    }

    #pragma unroll
    for (int mi = 0; mi < 2; mi++) {
        #pragma unroll
        for (int nj = 0; nj < 4; nj++) {
            int m0 = t0 + wm * 32 + mi * 16;
            int n0 = wn * 32 + nj * 8 + tig * 2;
            float* c = acc[mi][nj];
            size_t r0 = ((size_t)b * T_ + m0 + g) * H_ + n0;
            size_t r1 = ((size_t)b * T_ + m0 + g + 8) * H_ + n0;
            atomicAdd(&res[r0],     c[0]);
            atomicAdd(&res[r0 + 1], c[1]);
            atomicAdd(&res[r1],     c[2]);
            atomicAdd(&res[r1 + 1], c[3]);
        }
    }
}

// ---------------------------------------------------------------------------
extern "C" void kernel_launch(void* const* d_in, const int* in_sizes, int n_in,
                              void* d_out, int out_size) {
    (void)in_sizes; (void)n_in;
    const float* x  = (const float*)d_in[0];
    const float* Wq = (const float*)d_in[1];
    const float* Wk = (const float*)d_in[2];
    const float* Wv = (const float*)d_in[3];

    const size_t n_res  = (size_t)B_ * T_ * H_;
    const size_t n_attn = (size_t)B_ * T_ * T_;

    float* attn_scratch = nullptr;
    float* res_scratch = nullptr;
    float* rowsum = nullptr;
    cudaGetSymbolAddress((void**)&attn_scratch, g_attn_scratch);
    cudaGetSymbolAddress((void**)&res_scratch, g_res);
    cudaGetSymbolAddress((void**)&rowsum, g_rowsum);

    float* res;
    float* attn;
    if ((size_t)out_size == n_res + n_attn) {
        res  = (float*)d_out;
        attn = (float*)d_out + n_res;
    } else if ((size_t)out_size == n_attn) {
        attn = (float*)d_out;
        res  = res_scratch;
    } else {
        res  = (float*)d_out;
        attn = attn_scratch;
    }

    cudaFuncSetAttribute(proj_kernel,   cudaFuncAttributeMaxDynamicSharedMemorySize, PROJ_SMEM);
    cudaFuncSetAttribute(scores_kernel, cudaFuncAttributeMaxDynamicSharedMemorySize, SCORES_SMEM);
    cudaFuncSetAttribute(av_kernel,     cudaFuncAttributeMaxDynamicSharedMemorySize, AV_SMEM);

    cudaMemsetAsync(rowsum, 0, NROWS * sizeof(float));
    cudaMemsetAsync(res, 0, n_res * sizeof(float));
    proj_kernel<<<dim3(128, 3), 128, PROJ_SMEM>>>(x, Wq, Wk, Wv);
    scores_kernel<<<dim3(16, 32, 8), 128, SCORES_SMEM>>>(attn);
    av_kernel<<<dim3(8, 32, 8), 128, AV_SMEM>>>(attn, res);
}

// round 15
// speedup vs baseline: 1.6666x; 1.0250x over previous
#include <cuda_runtime.h>
#include <cuda_fp16.h>
#include <math.h>

#define B_ 8
#define T_ 2048
#define C_ 1024
#define H_ 64
#define NROWS (B_ * T_)   // 16384

__device__ float g_q[NROWS * H_];
__device__ float g_k[NROWS * H_];
__device__ float g_v[NROWS * H_];
__device__ float g_res[NROWS * H_];
__device__ float g_rowsum[NROWS];
__device__ __half g_e[(size_t)B_ * T_ * T_];        // fp16 unnormalized E
__device__ float g_attn_scratch[(size_t)B_ * T_ * T_];

// ---- tf32 helpers -----------------------------------------------------------
__device__ __forceinline__ unsigned tf32(float f) {
    unsigned r;
    asm("cvt.rna.tf32.f32 %0, %1;" : "=r"(r) : "f"(f));
    return r;
}
__device__ __forceinline__ uint4 tf32x4(float4 f) {
    uint4 u;
    u.x = tf32(f.x); u.y = tf32(f.y); u.z = tf32(f.z); u.w = tf32(f.w);
    return u;
}
// D += A(16x8,row) * B(8x8,col); tf32 in, fp32 accum
__device__ __forceinline__ void mma8(float* c, const unsigned* a, const unsigned* b) {
    asm("mma.sync.aligned.m16n8k8.row.col.f32.tf32.tf32.f32 "
        "{%0,%1,%2,%3},{%4,%5,%6,%7},{%8,%9},{%0,%1,%2,%3};"
        : "+f"(c[0]), "+f"(c[1]), "+f"(c[2]), "+f"(c[3])
        : "r"(a[0]), "r"(a[1]), "r"(a[2]), "r"(a[3]), "r"(b[0]), "r"(b[1]));
}
// Load a full 16x8 tf32 A-fragment in one instruction.
__device__ __forceinline__ void ldmA(unsigned* a, unsigned saddr) {
    asm volatile("ldmatrix.sync.aligned.m8n8.x4.shared.b16 {%0,%1,%2,%3}, [%4];"
        : "=r"(a[0]), "=r"(a[1]), "=r"(a[2]), "=r"(a[3]) : "r"(saddr));
}

// ---------------------------------------------------------------------------
// Kernel 1: QKV projection (known-good, 61.4us).
// grid=(128, 3), block=128 (4 warps: 2m x 2n). Block tile 128m x 64h.
// Warp tile 64m x 32h (mi=4, nj=4). A-fragments via ldmatrix.x4.
// ---------------------------------------------------------------------------
#define PROJ_SMEM (128 * 68 * 4 + 64 * 72 * 4)   // 53248 B
__global__ __launch_bounds__(128) void proj_kernel(const float* __restrict__ x,
                                                   const float* __restrict__ Wq,
                                                   const float* __restrict__ Wk,
                                                   const float* __restrict__ Wv) {
    extern __shared__ unsigned smu[];
    unsigned* Xs = smu;             // [128][68]
    unsigned* Ws = smu + 128 * 68;  // [64][72]

    const float* W; float* out;
    if (blockIdx.y == 0)      { W = Wq; out = g_q; }
    else if (blockIdx.y == 1) { W = Wk; out = g_k; }
    else                      { W = Wv; out = g_v; }

    const int row0 = blockIdx.x * 128;
    const int tid  = threadIdx.x;
    const int warp = tid >> 5;
    const int lane = tid & 31;
    const int g    = lane >> 2;    // 0..7
    const int tig  = lane & 3;     // 0..3
    const int wm   = warp >> 1;    // 0..1 (m)
    const int wn   = warp & 1;     // 0..1 (n)

    const unsigned xs_base = (unsigned)__cvta_generic_to_shared(Xs);
    const int lrow  = lane & 15;
    const int lkoff = (lane >> 4) * 4;

    float acc[4][4][4] = {};

    for (int k0 = 0; k0 < C_; k0 += 64) {
        #pragma unroll
        for (int it = 0; it < 16; it++) {
            int idx = tid + it * 128;
            int r = idx >> 4, c4 = idx & 15;
            *(uint4*)&Xs[r * 68 + c4 * 4] =
                tf32x4(*(const float4*)&x[(size_t)(row0 + r) * C_ + k0 + c4 * 4]);
        }
        #pragma unroll
        for (int it = 0; it < 8; it++) {
            int idx = tid + it * 128;
            int r = idx >> 4, c4 = idx & 15;
            *(uint4*)&Ws[r * 72 + c4 * 4] =
                tf32x4(*(const float4*)&W[(size_t)(k0 + r) * H_ + c4 * 4]);
        }
        __syncthreads();

        #pragma unroll
        for (int k8 = 0; k8 < 8; k8++) {
            const int kb = k8 * 8;
            unsigned a[4][4];
            #pragma unroll
            for (int mi = 0; mi < 4; mi++) {
                int m0 = wm * 64 + mi * 16;
                ldmA(a[mi], xs_base + (((m0 + lrow) * 68 + kb + lkoff) << 2));
            }
            #pragma unroll
            for (int nj = 0; nj < 4; nj++) {
                int n0 = wn * 32 + nj * 8;
                unsigned b[2];
                b[0] = Ws[(kb + tig) * 72 + n0 + g];
                b[1] = Ws[(kb + tig + 4) * 72 + n0 + g];
                #pragma unroll
                for (int mi = 0; mi < 4; mi++) mma8(acc[mi][nj], a[mi], b);
            }
        }
        __syncthreads();
    }

    #pragma unroll
    for (int mi = 0; mi < 4; mi++) {
        #pragma unroll
        for (int nj = 0; nj < 4; nj++) {
            int m0 = row0 + wm * 64 + mi * 16;
            int n0 = wn * 32 + nj * 8 + tig * 2;
            float* c = acc[mi][nj];
            *(float2*)&out[(size_t)(m0 + g) * H_ + n0]     = make_float2(c[0], c[1]);
            *(float2*)&out[(size_t)(m0 + g + 8) * H_ + n0] = make_float2(c[2], c[3]);
        }
    }
}

// ---------------------------------------------------------------------------
// Kernel 2: E = exp(Q@K^T / 32): lower tiles -> g_e as fp16; upper tiles ->
// zero-fill fp32 attn. rowsum atomics from fp32 values.
// grid=(16 s,32 t,8 b), block=128. Tile 64t x 128s.
// ---------------------------------------------------------------------------
#define SCORES_SMEM (64 * 68 * 4 + 128 * 68 * 4)   // 52224 B
__global__ __launch_bounds__(128, 4) void scores_kernel(float* __restrict__ attn) {
    const int s_t = blockIdx.x, t_t = blockIdx.y;
    const int b = blockIdx.z;
    const int t0 = t_t * 64, s0 = s_t * 128;
    const int tid = threadIdx.x;

    if (s0 > t0 + 63) {  // strictly-upper tile: zero fill final attn
        #pragma unroll
        for (int it = 0; it < 16; it++) {
            int idx = tid + it * 128;       // 2048 quads = 64 x 32
            int r = idx >> 5, c4 = idx & 31;
            *(float4*)&attn[((size_t)b * T_ + t0 + r) * T_ + s0 + c4 * 4] =
                make_float4(0.f, 0.f, 0.f, 0.f);
        }
        return;
    }

    extern __shared__ unsigned smu[];
    unsigned* Qs = smu;            // [64][68]
    unsigned* Ks = smu + 64 * 68;  // [128][68]

    const float* q = g_q + (size_t)b * T_ * H_;
    const float* k = g_k + (size_t)b * T_ * H_;

    #pragma unroll
    for (int it = 0; it < 8; it++) {
        int idx = tid + it * 128;
        int r = idx >> 4, c4 = idx & 15;
        *(uint4*)&Qs[r * 68 + c4 * 4] =
            tf32x4(*(const float4*)&q[(size_t)(t0 + r) * H_ + c4 * 4]);
    }
    #pragma unroll
    for (int it = 0; it < 16; it++) {
        int idx = tid + it * 128;
        int r = idx >> 4, c4 = idx & 15;
        *(uint4*)&Ks[r * 68 + c4 * 4] =
            tf32x4(*(const float4*)&k[(size_t)(s0 + r) * H_ + c4 * 4]);
    }
    __syncthreads();

    const int warp = tid >> 5;
    const int lane = tid & 31;
    const int g    = lane >> 2;
    const int tig  = lane & 3;
    const unsigned qs_base = (unsigned)__cvta_generic_to_shared(Qs);
    const int lrow  = lane & 15;
    const int lkoff = (lane >> 4) * 4;

    float acc[4][4][4] = {};
    #pragma unroll
    for (int k8 = 0; k8 < 8; k8++) {
        const int kb = k8 * 8;
        unsigned a[4][4];
        #pragma unroll
        for (int mi = 0; mi < 4; mi++) {
            ldmA(a[mi], qs_base + (((mi * 16 + lrow) * 68 + kb + lkoff) << 2));
        }
        #pragma unroll
        for (int nj = 0; nj < 4; nj++) {
            int n0 = warp * 32 + nj * 8;
            unsigned bb[2];
            bb[0] = Ks[(n0 + g) * 68 + kb + tig];
            bb[1] = Ks[(n0 + g) * 68 + kb + tig + 4];
            #pragma unroll
            for (int mi = 0; mi < 4; mi++) mma8(acc[mi][nj], a[mi], bb);
        }
    }

    const float sc = 0.03125f;  // 1/sqrt(1024)
    const bool need_mask = (s0 + 127 > t0);
    #pragma unroll
    for (int mi = 0; mi < 4; mi++) {
        const int trow0 = t0 + mi * 16 + g;
        const int trow1 = trow0 + 8;
        const size_t row0g = (size_t)b * T_ + trow0;
        const size_t row1g = (size_t)b * T_ + trow1;
        float rs0 = 0.f, rs1 = 0.f;
        #pragma unroll
        for (int nj = 0; nj < 4; nj++) {
            int col = s0 + warp * 32 + nj * 8 + tig * 2;
            float* c = acc[mi][nj];
            float e0 = (!need_mask || col     <= trow0) ? __expf(c[0] * sc) : 0.f;
            float e1 = (!need_mask || col + 1 <= trow0) ? __expf(c[1] * sc) : 0.f;
            float e2 = (!need_mask || col     <= trow1) ? __expf(c[2] * sc) : 0.f;
            float e3 = (!need_mask || col + 1 <= trow1) ? __expf(c[3] * sc) : 0.f;
            rs0 += e0 + e1; rs1 += e2 + e3;
            *(__half2*)&g_e[row0g * T_ + col] = __floats2half2_rn(e0, e1);
            *(__half2*)&g_e[row1g * T_ + col] = __floats2half2_rn(e2, e3);
        }
        rs0 += __shfl_xor_sync(0xffffffffu, rs0, 1);
        rs0 += __shfl_xor_sync(0xffffffffu, rs0, 2);
        rs1 += __shfl_xor_sync(0xffffffffu, rs1, 1);
        rs1 += __shfl_xor_sync(0xffffffffu, rs1, 2);
        if (tig == 0) {
            atomicAdd(&g_rowsum[row0g], rs0);
            atomicAdd(&g_rowsum[row1g], rs1);
        }
    }
}

// ---------------------------------------------------------------------------
// Kernel 3: res += (E/rowsum) @ V from fp16 E, split-K over 256-wide s-spans.
// Loader: read fp16 E, scale by 1/rowsum, write FINAL fp32 attn (sole writer
// of lower-tri), feed tf32 to MMA. grid=(8 spans, 32 t desc, 8 b), block=128.
// ---------------------------------------------------------------------------
#define AV_SMEM (64 * 68 * 4 + 64 * 72 * 4 + 64 * 4)   // 35904 B
__global__ __launch_bounds__(128, 5) void av_kernel(float* __restrict__ attn,
                                                    float* __restrict__ res) {
    const int sc   = blockIdx.x;
    const int t_t  = 31 - blockIdx.y;   // big tiles first
    const int b    = blockIdx.z;
    const int t0   = t_t * 64;
    if (sc * 256 > t0 + 63) return;

    extern __shared__ unsigned smu[];
    unsigned* As = smu;            // [64 t][68 s] tf32
    unsigned* Vs = smu + 64 * 68;  // [64 s][72 h] tf32
    float* sinv  = (float*)(smu + 64 * 68 + 64 * 72);

    const int tid = threadIdx.x;
    if (tid < 64) sinv[tid] = 1.f / g_rowsum[(size_t)b * T_ + t0 + tid];
    __syncthreads();

    const float* v = g_v + (size_t)b * T_ * H_;
    const int warp = tid >> 5;
    const int lane = tid & 31;
    const int g    = lane >> 2;
    const int tig  = lane & 3;
    const int wm   = warp >> 1;   // 0..1
    const int wn   = warp & 1;    // 0..1
    const unsigned as_base = (unsigned)__cvta_generic_to_shared(As);
    const int lrow  = lane & 15;
    const int lkoff = (lane >> 4) * 4;

    float acc[2][4][4] = {};

    #pragma unroll
    for (int c2 = 0; c2 < 4; c2++) {
        const int s0 = sc * 256 + c2 * 64;
        if (s0 > t0 + 63) break;

        // E loader: 64 rows x 64 s = 4096 halves; 8 halves (uint4) per thread/iter
        #pragma unroll
        for (int it = 0; it < 4; it++) {
            int idx = tid + it * 128;          // 512 uint4 = 64 x 8
            int r = idx >> 3, c8 = idx & 7;
            size_t rowg = (size_t)b * T_ + t0 + r;
            uint4 raw = *(const uint4*)&g_e[rowg * T_ + s0 + c8 * 8];
            float iv = sinv[r];
            float2 f0 = __half22float2(*(__half2*)&raw.x);
            float2 f1 = __half22float2(*(__half2*)&raw.y);
            float2 f2 = __half22float2(*(__half2*)&raw.z);
            float2 f3 = __half22float2(*(__half2*)&raw.w);
            float4 a0 = make_float4(f0.x * iv, f0.y * iv, f1.x * iv, f1.y * iv);
            float4 a1 = make_float4(f2.x * iv, f2.y * iv, f3.x * iv, f3.y * iv);
            float* ap = &attn[rowg * T_ + s0 + c8 * 8];
            *(float4*)ap       = a0;           // final normalized fp32 attn
            *(float4*)(ap + 4) = a1;
            *(uint4*)&As[r * 68 + c8 * 8]     = tf32x4(a0);
            *(uint4*)&As[r * 68 + c8 * 8 + 4] = tf32x4(a1);
        }
        #pragma unroll
        for (int it = 0; it < 8; it++) {
            int idx = tid + it * 128;
            int r = idx >> 4, c4 = idx & 15;
            *(uint4*)&Vs[r * 72 + c4 * 4] =
                tf32x4(*(const float4*)&v[(size_t)(s0 + r) * H_ + c4 * 4]);
        }
        __syncthreads();

        #pragma unroll
        for (int k8 = 0; k8 < 8; k8++) {
            const int kb = k8 * 8;
            unsigned a[2][4];
            #pragma unroll
            for (int mi = 0; mi < 2; mi++) {
                int m0 = wm * 32 + mi * 16;
                ldmA(a[mi], as_base + (((m0 + lrow) * 68 + kb + lkoff) << 2));
            }
            #pragma unroll
            for (int nj = 0; nj < 4; nj++) {
                int n0 = wn * 32 + nj * 8;
                unsigned bb[2];
                bb[0] = Vs[(kb + tig) * 72 + n0 + g];
                bb[1] = Vs[(kb + tig + 4) * 72 + n0 + g];
                #pragma unroll
                for (int mi = 0; mi < 2; mi++) mma8(acc[mi][nj], a[mi], bb);
            }
        }
        __syncthreads();
    }

    #pragma unroll
    for (int mi = 0; mi < 2; mi++) {
        #pragma unroll
        for (int nj = 0; nj < 4; nj++) {
            int m0 = t0 + wm * 32 + mi * 16;
            int n0 = wn * 32 + nj * 8 + tig * 2;
            float* c = acc[mi][nj];
            size_t r0 = ((size_t)b * T_ + m0 + g) * H_ + n0;
            size_t r1 = ((size_t)b * T_ + m0 + g + 8) * H_ + n0;
            atomicAdd(&res[r0],     c[0]);
            atomicAdd(&res[r0 + 1], c[1]);
            atomicAdd(&res[r1],     c[2]);
            atomicAdd(&res[r1 + 1], c[3]);
        }
    }
}

// ---------------------------------------------------------------------------
extern "C" void kernel_launch(void* const* d_in, const int* in_sizes, int n_in,
                              void* d_out, int out_size) {
    (void)in_sizes; (void)n_in;
    const float* x  = (const float*)d_in[0];
    const float* Wq = (const float*)d_in[1];
    const float* Wk = (const float*)d_in[2];
    const float* Wv = (const float*)d_in[3];

    const size_t n_res  = (size_t)B_ * T_ * H_;
    const size_t n_attn = (size_t)B_ * T_ * T_;

    float* attn_scratch = nullptr;
    float* res_scratch = nullptr;
    float* rowsum = nullptr;
    cudaGetSymbolAddress((void**)&attn_scratch, g_attn_scratch);
    cudaGetSymbolAddress((void**)&res_scratch, g_res);
    cudaGetSymbolAddress((void**)&rowsum, g_rowsum);

    float* res;
    float* attn;
    if ((size_t)out_size == n_res + n_attn) {
        res  = (float*)d_out;
        attn = (float*)d_out + n_res;
    } else if ((size_t)out_size == n_attn) {
        attn = (float*)d_out;
        res  = res_scratch;
    } else {
        res  = (float*)d_out;
        attn = attn_scratch;
    }

    cudaFuncSetAttribute(proj_kernel,   cudaFuncAttributeMaxDynamicSharedMemorySize, PROJ_SMEM);
    cudaFuncSetAttribute(scores_kernel, cudaFuncAttributeMaxDynamicSharedMemorySize, SCORES_SMEM);
    cudaFuncSetAttribute(av_kernel,     cudaFuncAttributeMaxDynamicSharedMemorySize, AV_SMEM);

    cudaMemsetAsync(rowsum, 0, NROWS * sizeof(float));
    cudaMemsetAsync(res, 0, n_res * sizeof(float));
    proj_kernel<<<dim3(128, 3), 128, PROJ_SMEM>>>(x, Wq, Wk, Wv);
    scores_kernel<<<dim3(16, 32, 8), 128, SCORES_SMEM>>>(attn);
    av_kernel<<<dim3(8, 32, 8), 128, AV_SMEM>>>(attn, res);
}

// round 16
// speedup vs baseline: 2.0891x; 1.2535x over previous
#include <cuda_runtime.h>
#include <cuda_fp16.h>
#include <math.h>

#define B_ 8
#define T_ 2048
#define C_ 1024
#define H_ 64
#define NROWS (B_ * T_)   // 16384

__device__ float g_q[NROWS * H_];
__device__ float g_k[NROWS * H_];
__device__ float g_v[NROWS * H_];
__device__ float g_res[NROWS * H_];
__device__ float g_rowsum[NROWS];
__device__ __half g_e[(size_t)B_ * T_ * T_];        // fp16 unnormalized E
__device__ float g_attn_scratch[(size_t)B_ * T_ * T_];

// ---- fp16 helpers -----------------------------------------------------------
__device__ __forceinline__ uint2 pack_h4(float4 f) {
    __half2 h0 = __floats2half2_rn(f.x, f.y);
    __half2 h1 = __floats2half2_rn(f.z, f.w);
    uint2 u;
    u.x = *(unsigned*)&h0;
    u.y = *(unsigned*)&h1;
    return u;
}
// D += A(16x16,row) * B(16x8,col); fp16 in, fp32 accum
__device__ __forceinline__ void mma16(float* c, const unsigned* a, const unsigned* b) {
    asm("mma.sync.aligned.m16n8k16.row.col.f32.f16.f16.f32 "
        "{%0,%1,%2,%3},{%4,%5,%6,%7},{%8,%9},{%0,%1,%2,%3};"
        : "+f"(c[0]), "+f"(c[1]), "+f"(c[2]), "+f"(c[3])
        : "r"(a[0]), "r"(a[1]), "r"(a[2]), "r"(a[3]), "r"(b[0]), "r"(b[1]));
}
// 16x16 fp16 A-fragment: addr = base + ((m0 + (lane&15))*pitch + kb + (lane>>4)*8)*2
__device__ __forceinline__ void ldmA16(unsigned* a, unsigned saddr) {
    asm volatile("ldmatrix.sync.aligned.m8n8.x4.shared.b16 {%0,%1,%2,%3}, [%4];"
        : "=r"(a[0]), "=r"(a[1]), "=r"(a[2]), "=r"(a[3]) : "r"(saddr));
}
// 16x8 fp16 B-fragment from k-row-major storage: addr lanes 0-15:
// base + ((kb + (lane&15))*pitch + n0)*2
__device__ __forceinline__ void ldmBT(unsigned* b, unsigned saddr) {
    asm volatile("ldmatrix.sync.aligned.m8n8.x2.trans.shared.b16 {%0,%1}, [%2];"
        : "=r"(b[0]), "=r"(b[1]) : "r"(saddr));
}

// ---------------------------------------------------------------------------
// Kernel 1: QKV projection, fp16 MMA. grid=(128, 3), block=128 (2m x 2n warps).
// Block tile 128m x 64h, K-chunk 64 (4 k16 steps). Warp tile 64m x 32h.
// smem: Xh[128][72]h + Wh[64][72]h = 27648 B.
// ---------------------------------------------------------------------------
#define PROJ_SMEM (128 * 72 * 2 + 64 * 72 * 2)
__global__ __launch_bounds__(128) void proj_kernel(const float* __restrict__ x,
                                                   const float* __restrict__ Wq,
                                                   const float* __restrict__ Wk,
                                                   const float* __restrict__ Wv) {
    extern __shared__ __half smh[];
    __half* Xh = smh;             // [128][72]
    __half* Wh = smh + 128 * 72;  // [64][72]

    const float* W; float* out;
    if (blockIdx.y == 0)      { W = Wq; out = g_q; }
    else if (blockIdx.y == 1) { W = Wk; out = g_k; }
    else                      { W = Wv; out = g_v; }

    const int row0 = blockIdx.x * 128;
    const int tid  = threadIdx.x;
    const int warp = tid >> 5;
    const int lane = tid & 31;
    const int g    = lane >> 2;
    const int tig  = lane & 3;
    const int wm   = warp >> 1;
    const int wn   = warp & 1;

    const unsigned xh_base = (unsigned)__cvta_generic_to_shared(Xh);
    const unsigned wh_base = (unsigned)__cvta_generic_to_shared(Wh);
    const int l16   = lane & 15;
    const int koff8 = (lane >> 4) * 8;

    float acc[4][4][4] = {};

    for (int k0 = 0; k0 < C_; k0 += 64) {
        #pragma unroll
        for (int it = 0; it < 16; it++) {
            int idx = tid + it * 128;         // 2048 float4 = 128 x 16
            int r = idx >> 4, c4 = idx & 15;
            *(uint2*)&Xh[r * 72 + c4 * 4] =
                pack_h4(*(const float4*)&x[(size_t)(row0 + r) * C_ + k0 + c4 * 4]);
        }
        #pragma unroll
        for (int it = 0; it < 8; it++) {
            int idx = tid + it * 128;         // 1024 float4 = 64 x 16
            int r = idx >> 4, c4 = idx & 15;
            *(uint2*)&Wh[r * 72 + c4 * 4] =
                pack_h4(*(const float4*)&W[(size_t)(k0 + r) * H_ + c4 * 4]);
        }
        __syncthreads();

        #pragma unroll
        for (int k16 = 0; k16 < 4; k16++) {
            const int kb = k16 * 16;
            unsigned a[4][4];
            #pragma unroll
            for (int mi = 0; mi < 4; mi++) {
                int m0 = wm * 64 + mi * 16;
                ldmA16(a[mi], xh_base + (((m0 + l16) * 72 + kb + koff8) << 1));
            }
            #pragma unroll
            for (int nj = 0; nj < 4; nj++) {
                int n0 = wn * 32 + nj * 8;
                unsigned b[2];
                ldmBT(b, wh_base + (((kb + l16) * 72 + n0) << 1));
                #pragma unroll
                for (int mi = 0; mi < 4; mi++) mma16(acc[mi][nj], a[mi], b);
            }
        }
        __syncthreads();
    }

    #pragma unroll
    for (int mi = 0; mi < 4; mi++) {
        #pragma unroll
        for (int nj = 0; nj < 4; nj++) {
            int m0 = row0 + wm * 64 + mi * 16;
            int n0 = wn * 32 + nj * 8 + tig * 2;
            float* c = acc[mi][nj];
            *(float2*)&out[(size_t)(m0 + g) * H_ + n0]     = make_float2(c[0], c[1]);
            *(float2*)&out[(size_t)(m0 + g + 8) * H_ + n0] = make_float2(c[2], c[3]);
        }
    }
}

// ---------------------------------------------------------------------------
// Kernel 2: E = exp(Q@K^T / 32), fp16 MMA. Lower tiles -> g_e fp16 + rowsum;
// upper tiles -> zero-fill fp32 attn. grid=(16 s,32 t,8 b), block=128.
// Tile 64t x 128s. smem: Qh[64][72]h + Kh[128][72]h = 27648 B.
// B-fragments from Kh rows are k(h)-contiguous -> plain 32-bit LDS.
// ---------------------------------------------------------------------------
#define SCORES_SMEM (64 * 72 * 2 + 128 * 72 * 2)
__global__ __launch_bounds__(128, 4) void scores_kernel(float* __restrict__ attn) {
    const int s_t = blockIdx.x, t_t = blockIdx.y;
    const int b = blockIdx.z;
    const int t0 = t_t * 64, s0 = s_t * 128;
    const int tid = threadIdx.x;

    if (s0 > t0 + 63) {  // strictly-upper tile: zero fill final attn
        #pragma unroll
        for (int it = 0; it < 16; it++) {
            int idx = tid + it * 128;
            int r = idx >> 5, c4 = idx & 31;
            *(float4*)&attn[((size_t)b * T_ + t0 + r) * T_ + s0 + c4 * 4] =
                make_float4(0.f, 0.f, 0.f, 0.f);
        }
        return;
    }

    extern __shared__ __half smh[];
    __half* Qh = smh;            // [64][72]
    __half* Kh = smh + 64 * 72;  // [128][72]

    const float* q = g_q + (size_t)b * T_ * H_;
    const float* k = g_k + (size_t)b * T_ * H_;

    #pragma unroll
    for (int it = 0; it < 8; it++) {
        int idx = tid + it * 128;
        int r = idx >> 4, c4 = idx & 15;
        *(uint2*)&Qh[r * 72 + c4 * 4] =
            pack_h4(*(const float4*)&q[(size_t)(t0 + r) * H_ + c4 * 4]);
    }
    #pragma unroll
    for (int it = 0; it < 16; it++) {
        int idx = tid + it * 128;
        int r = idx >> 4, c4 = idx & 15;
        *(uint2*)&Kh[r * 72 + c4 * 4] =
            pack_h4(*(const float4*)&k[(size_t)(s0 + r) * H_ + c4 * 4]);
    }
    __syncthreads();

    const int warp = tid >> 5;
    const int lane = tid & 31;
    const int g    = lane >> 2;
    const int tig  = lane & 3;
    const unsigned qh_base = (unsigned)__cvta_generic_to_shared(Qh);
    const int l16   = lane & 15;
    const int koff8 = (lane >> 4) * 8;

    float acc[4][4][4] = {};
    #pragma unroll
    for (int k16 = 0; k16 < 4; k16++) {
        const int kb = k16 * 16;
        unsigned a[4][4];
        #pragma unroll
        for (int mi = 0; mi < 4; mi++) {
            ldmA16(a[mi], qh_base + (((mi * 16 + l16) * 72 + kb + koff8) << 1));
        }
        #pragma unroll
        for (int nj = 0; nj < 4; nj++) {
            int n0 = warp * 32 + nj * 8;
            unsigned bb[2];
            bb[0] = *(unsigned*)&Kh[(n0 + g) * 72 + kb + tig * 2];
            bb[1] = *(unsigned*)&Kh[(n0 + g) * 72 + kb + tig * 2 + 8];
            #pragma unroll
            for (int mi = 0; mi < 4; mi++) mma16(acc[mi][nj], a[mi], bb);
        }
    }

    const float sc = 0.03125f;  // 1/sqrt(1024)
    const bool need_mask = (s0 + 127 > t0);
    #pragma unroll
    for (int mi = 0; mi < 4; mi++) {
        const int trow0 = t0 + mi * 16 + g;
        const int trow1 = trow0 + 8;
        const size_t row0g = (size_t)b * T_ + trow0;
        const size_t row1g = (size_t)b * T_ + trow1;
        float rs0 = 0.f, rs1 = 0.f;
        #pragma unroll
        for (int nj = 0; nj < 4; nj++) {
            int col = s0 + warp * 32 + nj * 8 + tig * 2;
            float* c = acc[mi][nj];
            float e0 = (!need_mask || col     <= trow0) ? __expf(c[0] * sc) : 0.f;
            float e1 = (!need_mask || col + 1 <= trow0) ? __expf(c[1] * sc) : 0.f;
            float e2 = (!need_mask || col     <= trow1) ? __expf(c[2] * sc) : 0.f;
            float e3 = (!need_mask || col + 1 <= trow1) ? __expf(c[3] * sc) : 0.f;
            rs0 += e0 + e1; rs1 += e2 + e3;
            *(__half2*)&g_e[row0g * T_ + col] = __floats2half2_rn(e0, e1);
            *(__half2*)&g_e[row1g * T_ + col] = __floats2half2_rn(e2, e3);
        }
        rs0 += __shfl_xor_sync(0xffffffffu, rs0, 1);
        rs0 += __shfl_xor_sync(0xffffffffu, rs0, 2);
        rs1 += __shfl_xor_sync(0xffffffffu, rs1, 1);
        rs1 += __shfl_xor_sync(0xffffffffu, rs1, 2);
        if (tig == 0) {
            atomicAdd(&g_rowsum[row0g], rs0);
            atomicAdd(&g_rowsum[row1g], rs1);
        }
    }
}

// ---------------------------------------------------------------------------
// Kernel 3: res += (E/rowsum) @ V, fp16 MMA, split-K over 256-wide s-spans.
// Loader: fp16 E -> scale -> final fp32 attn + fp16 As. V via ldmBT.
// grid=(8 spans, 32 t desc, 8 b), block=128 (4 warps 2x2). Tile 64t x 64h.
// smem: As[64][72]h + Vh[64][72]h + sinv = 18688 B.
// ---------------------------------------------------------------------------
#define AV_SMEM (64 * 72 * 2 + 64 * 72 * 2 + 64 * 4)
__global__ __launch_bounds__(128, 5) void av_kernel(float* __restrict__ attn,
                                                    float* __restrict__ res) {
    const int sc   = blockIdx.x;
    const int t_t  = 31 - blockIdx.y;   // big tiles first
    const int b    = blockIdx.z;
    const int t0   = t_t * 64;
    if (sc * 256 > t0 + 63) return;

    extern __shared__ __half smh[];
    __half* As = smh;            // [64][72]
    __half* Vh = smh + 64 * 72;  // [64][72]
    float* sinv = (float*)(smh + 2 * 64 * 72);

    const int tid = threadIdx.x;
    if (tid < 64) sinv[tid] = 1.f / g_rowsum[(size_t)b * T_ + t0 + tid];
    __syncthreads();

    const float* v = g_v + (size_t)b * T_ * H_;
    const int warp = tid >> 5;
    const int lane = tid & 31;
    const int g    = lane >> 2;
    const int tig  = lane & 3;
    const int wm   = warp >> 1;
    const int wn   = warp & 1;
    const unsigned as_base = (unsigned)__cvta_generic_to_shared(As);
    const unsigned vh_base = (unsigned)__cvta_generic_to_shared(Vh);
    const int l16   = lane & 15;
    const int koff8 = (lane >> 4) * 8;

    float acc[2][4][4] = {};

    #pragma unroll
    for (int c2 = 0; c2 < 4; c2++) {
        const int s0 = sc * 256 + c2 * 64;
        if (s0 > t0 + 63) break;

        // E loader: 64 rows x 64 s = 4096 halves; 8 halves (uint4) per thread/iter
        #pragma unroll
        for (int it = 0; it < 4; it++) {
            int idx = tid + it * 128;          // 512 uint4 = 64 x 8
            int r = idx >> 3, c8 = idx & 7;
            size_t rowg = (size_t)b * T_ + t0 + r;
            uint4 raw = *(const uint4*)&g_e[rowg * T_ + s0 + c8 * 8];
            float iv = sinv[r];
            float2 f0 = __half22float2(*(__half2*)&raw.x);
            float2 f1 = __half22float2(*(__half2*)&raw.y);
            float2 f2 = __half22float2(*(__half2*)&raw.z);
            float2 f3 = __half22float2(*(__half2*)&raw.w);
            float4 a0 = make_float4(f0.x * iv, f0.y * iv, f1.x * iv, f1.y * iv);
            float4 a1 = make_float4(f2.x * iv, f2.y * iv, f3.x * iv, f3.y * iv);
            float* ap = &attn[rowg * T_ + s0 + c8 * 8];
            *(float4*)ap       = a0;           // final normalized fp32 attn
            *(float4*)(ap + 4) = a1;
            uint2 p0 = pack_h4(a0);
            uint2 p1 = pack_h4(a1);
            *(uint4*)&As[r * 72 + c8 * 8] = make_uint4(p0.x, p0.y, p1.x, p1.y);
        }
        #pragma unroll
        for (int it = 0; it < 8; it++) {
            int idx = tid + it * 128;
            int r = idx >> 4, c4 = idx & 15;
            *(uint2*)&Vh[r * 72 + c4 * 4] =
                pack_h4(*(const float4*)&v[(size_t)(s0 + r) * H_ + c4 * 4]);
        }
        __syncthreads();

        #pragma unroll
        for (int k16 = 0; k16 < 4; k16++) {
            const int kb = k16 * 16;
            unsigned a[2][4];
            #pragma unroll
            for (int mi = 0; mi < 2; mi++) {
                int m0 = wm * 32 + mi * 16;
                ldmA16(a[mi], as_base + (((m0 + l16) * 72 + kb + koff8) << 1));
            }
            #pragma unroll
            for (int nj = 0; nj < 4; nj++) {
                int n0 = wn * 32 + nj * 8;
                unsigned bb[2];
                ldmBT(bb, vh_base + (((kb + l16) * 72 + n0) << 1));
                #pragma unroll
                for (int mi = 0; mi < 2; mi++) mma16(acc[mi][nj], a[mi], bb);
            }
        }
        __syncthreads();
    }

    #pragma unroll
    for (int mi = 0; mi < 2; mi++) {
        #pragma unroll
        for (int nj = 0; nj < 4; nj++) {
            int m0 = t0 + wm * 32 + mi * 16;
            int n0 = wn * 32 + nj * 8 + tig * 2;
            float* c = acc[mi][nj];
            size_t r0 = ((size_t)b * T_ + m0 + g) * H_ + n0;
            size_t r1 = ((size_t)b * T_ + m0 + g + 8) * H_ + n0;
            atomicAdd(&res[r0],     c[0]);
            atomicAdd(&res[r0 + 1], c[1]);
            atomicAdd(&res[r1],     c[2]);
            atomicAdd(&res[r1 + 1], c[3]);
        }
    }
}

// ---------------------------------------------------------------------------
extern "C" void kernel_launch(void* const* d_in, const int* in_sizes, int n_in,
                              void* d_out, int out_size) {
    (void)in_sizes; (void)n_in;
    const float* x  = (const float*)d_in[0];
    const float* Wq = (const float*)d_in[1];
    const float* Wk = (const float*)d_in[2];
    const float* Wv = (const float*)d_in[3];

    const size_t n_res  = (size_t)B_ * T_ * H_;
    const size_t n_attn = (size_t)B_ * T_ * T_;

    float* attn_scratch = nullptr;
    float* res_scratch = nullptr;
    float* rowsum = nullptr;
    cudaGetSymbolAddress((void**)&attn_scratch, g_attn_scratch);
    cudaGetSymbolAddress((void**)&res_scratch, g_res);
    cudaGetSymbolAddress((void**)&rowsum, g_rowsum);

    float* res;
    float* attn;
    if ((size_t)out_size == n_res + n_attn) {
        res  = (float*)d_out;
        attn = (float*)d_out + n_res;
    } else if ((size_t)out_size == n_attn) {
        attn = (float*)d_out;
        res  = res_scratch;
    } else {
        res  = (float*)d_out;
        attn = attn_scratch;
    }

    cudaFuncSetAttribute(proj_kernel,   cudaFuncAttributeMaxDynamicSharedMemorySize, PROJ_SMEM);
    cudaFuncSetAttribute(scores_kernel, cudaFuncAttributeMaxDynamicSharedMemorySize, SCORES_SMEM);
    cudaFuncSetAttribute(av_kernel,     cudaFuncAttributeMaxDynamicSharedMemorySize, AV_SMEM);

    cudaMemsetAsync(rowsum, 0, NROWS * sizeof(float));
    cudaMemsetAsync(res, 0, n_res * sizeof(float));
    proj_kernel<<<dim3(128, 3), 128, PROJ_SMEM>>>(x, Wq, Wk, Wv);
    scores_kernel<<<dim3(16, 32, 8), 128, SCORES_SMEM>>>(attn);
    av_kernel<<<dim3(8, 32, 8), 128, AV_SMEM>>>(attn, res);
}